// round 6
// baseline (speedup 1.0000x reference)
#include <cuda_runtime.h>
#include <cuda_fp16.h>
#include <math.h>

// ---------------- problem constants ----------------
constexpr int NN = 20000;
constexpr int EE = 320000;
constexpr int RB = 20;    // NRBF
constexpr float PI_F = 3.14159265358979323846f;
constexpr float EPS3 = 3e-15f;

// pre-split weight bank offsets (elements), transposed [N][K] layout
constexpr int OW_MW1 = 0;                      // 128x128
constexpr int OW_MW2 = 16384;                  // 384x128
constexpr int OW_UW1 = 65536;                  // 128x256
constexpr int OW_UW2 = 98304;                  // 384x128
constexpr int OW_EW1 = 147456;                 // 256x128
constexpr int OW_EW2 = 180224;                 // 128x256
constexpr int LSTR   = 212992;                 // per-layer stride
constexpr int OW_RO  = 3 * LSTR;               // 256x128
constexpr int WTOT   = OW_RO + 32768;

// ---------------- device scratch ----------------
__device__ float g_rbf [(size_t)EE * RB];
__device__ float g_env [EE];
__device__ float g_unit[(size_t)EE * 3];
__device__ float g_eij [(size_t)EE * 128];
__device__ float g_s   [(size_t)NN * 128];
__device__ float g_v0  [(size_t)NN * 384];
__device__ float g_v1  [(size_t)NN * 384];
__device__ float g_phi [(size_t)NN * 384];
__device__ float g_uv  [(size_t)NN * 384];
__device__ float g_dot [(size_t)NN * 128];
__device__ float g_stk [(size_t)NN * 256];
__device__ float g_spl [(size_t)NN * 384];
__device__ float g_t   [(size_t)NN * 256];
__device__ __half g_h1h[(size_t)NN * 128];
__device__ __half g_h1l[(size_t)NN * 128];
__device__ __half g_wh [WTOT];
__device__ __half g_wl [WTOT];
// CSR by src
__device__ int g_rowptr[NN + 1];
__device__ int g_cursor[NN];
__device__ int g_perm  [EE];

__device__ __forceinline__ float swish(float x) {
    return x / (1.f + expf(-x));
}

__device__ __forceinline__ void split_h(float x, __half& hi, __half& lo) {
    hi = __float2half_rn(x);
    lo = __float2half_rn(x - __half2float(hi));
}

__device__ __forceinline__ void hmma(float* d, const unsigned* a, const unsigned* b) {
    asm volatile(
        "mma.sync.aligned.m16n8k16.row.col.f32.f16.f16.f32 "
        "{%0,%1,%2,%3}, {%4,%5,%6,%7}, {%8,%9}, {%0,%1,%2,%3};"
        : "+f"(d[0]), "+f"(d[1]), "+f"(d[2]), "+f"(d[3])
        : "r"(a[0]), "r"(a[1]), "r"(a[2]), "r"(a[3]), "r"(b[0]), "r"(b[1]));
}

// ---------------- weight transpose + split: W[K][N] -> Dh/Dl [N][K] ----------------
__global__ void wsplit_kernel(const float* __restrict__ W, __half* __restrict__ Dh,
                              __half* __restrict__ Dl, int K, int N) {
    __shared__ float tile[32][33];
    int tx = threadIdx.x, ty = threadIdx.y;
    int n0 = blockIdx.x * 32, k0 = blockIdx.y * 32;
    #pragma unroll
    for (int r = ty; r < 32; r += 8) {
        int k = k0 + r, n = n0 + tx;
        tile[r][tx] = (k < K && n < N) ? W[(size_t)k * N + n] : 0.f;
    }
    __syncthreads();
    #pragma unroll
    for (int r = ty; r < 32; r += 8) {
        int n = n0 + r, k = k0 + tx;
        if (n < N && k < K) {
            __half hi, lo;
            split_h(tile[tx][r], hi, lo);
            Dh[(size_t)n * K + k] = hi;
            Dl[(size_t)n * K + k] = lo;
        }
    }
}

// ---------------- init ----------------
__global__ void init_kernel(const float* __restrict__ emb, const int* __restrict__ z,
                            float* __restrict__ out) {
    int stride = gridDim.x * blockDim.x;
    for (int i = blockIdx.x * blockDim.x + threadIdx.x; i < NN * 384; i += stride) {
        g_v0[i] = 0.f;
        if (i < NN * 128) {
            int n = i >> 7, f = i & 127;
            g_s[i] = emb[z[n] * 128 + f];
        }
        if (i < NN * 3) out[i] = 0.f;
    }
}

// ---------------- CSR build ----------------
__global__ void zero_rowptr() {
    int i = blockIdx.x * blockDim.x + threadIdx.x;
    if (i <= NN) g_rowptr[i] = 0;
}
__global__ void hist_kernel(const int* __restrict__ nbrs) {
    int e = blockIdx.x * blockDim.x + threadIdx.x;
    if (e < EE) atomicAdd(&g_rowptr[nbrs[2 * e] + 1], 1);
}
__global__ void scan_kernel() {
    __shared__ int sm[1024];
    __shared__ int carry;
    int t = threadIdx.x;
    if (t == 0) carry = 0;
    __syncthreads();
    int nch = (NN + 1 + 1023) / 1024;
    for (int c = 0; c < nch; c++) {
        int i = c * 1024 + t;
        int v = (i <= NN) ? g_rowptr[i] : 0;
        sm[t] = v;
        __syncthreads();
        #pragma unroll
        for (int off = 1; off < 1024; off <<= 1) {
            int x = (t >= off) ? sm[t - off] : 0;
            __syncthreads();
            sm[t] += x;
            __syncthreads();
        }
        if (i <= NN) g_rowptr[i] = sm[t] + carry;
        int total = sm[1023];
        __syncthreads();
        if (t == 0) carry += total;
        __syncthreads();
    }
}
__global__ void cursor_init() {
    int i = blockIdx.x * blockDim.x + threadIdx.x;
    if (i < NN) g_cursor[i] = g_rowptr[i];
}
__global__ void scatter_kernel(const int* __restrict__ nbrs) {
    int e = blockIdx.x * blockDim.x + threadIdx.x;
    if (e < EE) {
        int pos = atomicAdd(&g_cursor[nbrs[2 * e]], 1);
        g_perm[pos] = e;
    }
}

// ---------------- per-edge geometry ----------------
__global__ void prep_kernel(const float* __restrict__ xyz, const int* __restrict__ nbrs) {
    int e = blockIdx.x * blockDim.x + threadIdx.x;
    if (e >= EE) return;
    int s = nbrs[2 * e], d = nbrs[2 * e + 1];
    float dx = xyz[d * 3 + 0] - xyz[s * 3 + 0];
    float dy = xyz[d * 3 + 1] - xyz[s * 3 + 1];
    float dz = xyz[d * 3 + 2] - xyz[s * 3 + 2];
    float d2 = dx * dx + dy * dy + dz * dz + EPS3;
    float dist = sqrtf(d2);
    float inv = 1.f / dist;
    g_unit[(size_t)e * 3 + 0] = dx * inv;
    g_unit[(size_t)e * 3 + 1] = dy * inv;
    g_unit[(size_t)e * 3 + 2] = dz * inv;
    float env = (dist < 5.f) ? 0.5f * (cosf(dist * (PI_F / 5.f)) + 1.f) : 0.f;
    g_env[e] = env;
    float base = dist * (PI_F / 5.f);
    #pragma unroll
    for (int k = 1; k <= RB; k++) {
        g_rbf[(size_t)e * RB + (k - 1)] = sinf(base * (float)k) * inv;
    }
}

// ---------------- small-K GEMM (rbf K=20 init of e_ij) ----------------
template<int K, int NC>
__global__ void __launch_bounds__(NC)
mlp_gemm_small(const float* __restrict__ A, const float* __restrict__ W,
               const float* __restrict__ bias, float* __restrict__ C,
               const float* __restrict__ env, int M) {
    constexpr int TM = 32;
    constexpr int PAD = 36;
    __shared__ __align__(16) float As[K * PAD];
    int m0 = blockIdx.x * TM;
    int tid = threadIdx.x;
    for (int i = tid; i < TM * K; i += NC) {
        int r = i / K, c = i - r * K;
        int m = m0 + r;
        As[c * PAD + r] = (m < M) ? A[(size_t)m * K + c] : 0.f;
    }
    __syncthreads();
    float acc[TM];
    #pragma unroll
    for (int r = 0; r < TM; r++) acc[r] = 0.f;
    const float* Wj = W + tid;
    #pragma unroll
    for (int k = 0; k < K; k++) {
        float w = Wj[k * NC];
        const float4* row = reinterpret_cast<const float4*>(&As[k * PAD]);
        #pragma unroll
        for (int r4 = 0; r4 < TM / 4; r4++) {
            float4 a = row[r4];
            acc[r4 * 4 + 0] = fmaf(a.x, w, acc[r4 * 4 + 0]);
            acc[r4 * 4 + 1] = fmaf(a.y, w, acc[r4 * 4 + 1]);
            acc[r4 * 4 + 2] = fmaf(a.z, w, acc[r4 * 4 + 2]);
            acc[r4 * 4 + 3] = fmaf(a.w, w, acc[r4 * 4 + 3]);
        }
    }
    float bj = bias[tid];
    #pragma unroll
    for (int r = 0; r < TM; r++) {
        int m = m0 + r;
        if (m >= M) break;
        C[(size_t)m * NC + tid] = (acc[r] + bj) * env[m];
    }
}

// ================ generic HMMA GEMM ================
// C[:, col0:+128] (op)= A' @ W[:, col0:+128] + bias_scale*b
// A' row m: GATHER_SWISH ? swish(A[src]+A[dst]) : A[m]
// B comes PRE-SPLIT + transposed: Wh/Wl are [Ntot][K], row = global out col.
// AIN_HALF: A comes pre-split (Ahg/Alg, [M][K] halves).
// SPLIT_OUT: write C as pre-split halves (Ch/Cl) instead of fp32.
constexpr int HP = 72;
template<int K, bool GATHER_SWISH, bool SWISH_OUT, bool ACCUM, bool AIN_HALF, bool SPLIT_OUT>
__global__ void __launch_bounds__(256)
hmma_gemm(const float* __restrict__ Ain,
          const __half* __restrict__ Ahg, const __half* __restrict__ Alg,
          const __half* __restrict__ Wh, const __half* __restrict__ Wl, int ldw,
          const float* __restrict__ bias, float bias_scale,
          float* __restrict__ C, __half* __restrict__ Ch, __half* __restrict__ Cl,
          const int* __restrict__ nbrs, int M) {
    extern __shared__ __align__(16) __half hsm[];
    __half* Ah = hsm;
    __half* Al = Ah + 128 * HP;
    __half* Bh = Al + 128 * HP;
    __half* Bl = Bh + 128 * HP;
    __shared__ int s_src[128], s_dst[128];

    int tid = threadIdx.x;
    int wid = tid >> 5, lane = tid & 31;
    int g = lane >> 2, tq = lane & 3;
    int wm0 = (wid & 3) * 32;
    int n0w = (wid >> 2) * 64;
    int m0b = blockIdx.x * 128;
    int col0 = blockIdx.y * 128;

    if (GATHER_SWISH && tid < 128) {
        int m = m0b + tid;
        s_src[tid] = (m < M) ? nbrs[2 * m] : 0;
        s_dst[tid] = (m < M) ? nbrs[2 * m + 1] : 0;
    }

    float acc[2][8][4];
    #pragma unroll
    for (int mi = 0; mi < 2; mi++)
        #pragma unroll
        for (int ni = 0; ni < 8; ni++)
            #pragma unroll
            for (int j = 0; j < 4; j++) acc[mi][ni][j] = 0.f;

    constexpr int NCH = K / 64;
    for (int kc = 0; kc < NCH; kc++) {
        __syncthreads();
        // ---- stage A chunk [128 rows][64 k] ----
        if (AIN_HALF) {
            for (int idx = tid; idx < 128 * 8; idx += 256) {
                int r = idx >> 3, q8 = (idx & 7) * 8;
                int m = m0b + r;
                uint4 vh = make_uint4(0, 0, 0, 0), vl = vh;
                if (m < M) {
                    vh = *(const uint4*)&Ahg[(size_t)m * K + kc * 64 + q8];
                    vl = *(const uint4*)&Alg[(size_t)m * K + kc * 64 + q8];
                }
                *(uint4*)&Ah[r * HP + q8] = vh;
                *(uint4*)&Al[r * HP + q8] = vl;
            }
        } else {
            for (int idx = tid; idx < 128 * 16; idx += 256) {
                int r = idx >> 4, k = (idx & 15) * 4;
                int m = m0b + r;
                float x[4] = {0.f, 0.f, 0.f, 0.f};
                if (m < M) {
                    if (GATHER_SWISH) {
                        float4 a = *(const float4*)&Ain[(size_t)s_src[r] * K + kc * 64 + k];
                        float4 b = *(const float4*)&Ain[(size_t)s_dst[r] * K + kc * 64 + k];
                        x[0] = swish(a.x + b.x); x[1] = swish(a.y + b.y);
                        x[2] = swish(a.z + b.z); x[3] = swish(a.w + b.w);
                    } else {
                        float4 a = *(const float4*)&Ain[(size_t)m * K + kc * 64 + k];
                        x[0] = a.x; x[1] = a.y; x[2] = a.z; x[3] = a.w;
                    }
                }
                #pragma unroll
                for (int j = 0; j < 4; j++) {
                    __half hi, lo;
                    split_h(x[j], hi, lo);
                    Ah[r * HP + k + j] = hi;
                    Al[r * HP + k + j] = lo;
                }
            }
        }
        // ---- stage B chunk: straight copy of pre-split transposed weights ----
        for (int idx = tid; idx < 128 * 8; idx += 256) {
            int n = idx >> 3, q8 = (idx & 7) * 8;
            *(uint4*)&Bh[n * HP + q8] =
                *(const uint4*)&Wh[(size_t)(col0 + n) * K + kc * 64 + q8];
            *(uint4*)&Bl[n * HP + q8] =
                *(const uint4*)&Wl[(size_t)(col0 + n) * K + kc * 64 + q8];
        }
        __syncthreads();

        #pragma unroll
        for (int ks = 0; ks < 4; ks++) {
            int kl = ks * 16;
            unsigned ah[2][4], al[2][4];
            #pragma unroll
            for (int mi = 0; mi < 2; mi++) {
                int r = wm0 + mi * 16;
                ah[mi][0] = *(const unsigned*)&Ah[(r + g) * HP + kl + 2 * tq];
                ah[mi][1] = *(const unsigned*)&Ah[(r + g + 8) * HP + kl + 2 * tq];
                ah[mi][2] = *(const unsigned*)&Ah[(r + g) * HP + kl + 8 + 2 * tq];
                ah[mi][3] = *(const unsigned*)&Ah[(r + g + 8) * HP + kl + 8 + 2 * tq];
                al[mi][0] = *(const unsigned*)&Al[(r + g) * HP + kl + 2 * tq];
                al[mi][1] = *(const unsigned*)&Al[(r + g + 8) * HP + kl + 2 * tq];
                al[mi][2] = *(const unsigned*)&Al[(r + g) * HP + kl + 8 + 2 * tq];
                al[mi][3] = *(const unsigned*)&Al[(r + g + 8) * HP + kl + 8 + 2 * tq];
            }
            #pragma unroll
            for (int ni = 0; ni < 8; ni++) {
                int n = n0w + ni * 8 + g;
                unsigned bh[2], bl[2];
                bh[0] = *(const unsigned*)&Bh[n * HP + kl + 2 * tq];
                bh[1] = *(const unsigned*)&Bh[n * HP + kl + 8 + 2 * tq];
                bl[0] = *(const unsigned*)&Bl[n * HP + kl + 2 * tq];
                bl[1] = *(const unsigned*)&Bl[n * HP + kl + 8 + 2 * tq];
                #pragma unroll
                for (int mi = 0; mi < 2; mi++) {
                    hmma(acc[mi][ni], ah[mi], bh);
                    hmma(acc[mi][ni], ah[mi], bl);
                    hmma(acc[mi][ni], al[mi], bh);
                }
            }
        }
    }

    // ---- epilogue ----
    #pragma unroll
    for (int mi = 0; mi < 2; mi++) {
        #pragma unroll
        for (int ni = 0; ni < 8; ni++) {
            int col = n0w + ni * 8 + 2 * tq;
            float2 bb = *(const float2*)&bias[col0 + col];
            bb.x *= bias_scale; bb.y *= bias_scale;
            #pragma unroll
            for (int h = 0; h < 2; h++) {
                int m = m0b + wm0 + mi * 16 + g + h * 8;
                if (m >= M) continue;
                float2 o;
                o.x = acc[mi][ni][2 * h + 0] + bb.x;
                o.y = acc[mi][ni][2 * h + 1] + bb.y;
                if (SWISH_OUT) { o.x = swish(o.x); o.y = swish(o.y); }
                size_t ci = (size_t)m * ldw + col0 + col;
                if (SPLIT_OUT) {
                    __half hx, lx, hy, ly;
                    split_h(o.x, hx, lx);
                    split_h(o.y, hy, ly);
                    *(unsigned*)&Ch[ci] =
                        (unsigned)*(unsigned short*)&hx | ((unsigned)*(unsigned short*)&hy << 16);
                    *(unsigned*)&Cl[ci] =
                        (unsigned)*(unsigned short*)&lx | ((unsigned)*(unsigned short*)&ly << 16);
                } else {
                    if (ACCUM) {
                        float2 old = *(const float2*)&C[ci];
                        o.x += old.x; o.y += old.y;
                    }
                    *(float2*)&C[ci] = o;
                }
            }
        }
    }
}

// ---------------- CSR message pass ----------------
__global__ void __launch_bounds__(128)
msg2_kernel(const int* __restrict__ nbrs, const float* __restrict__ dw,
            const float* __restrict__ db, int sel) {
    int n = blockIdx.x;
    int t = threadIdx.x;

    float dwr0[RB], dwr1[RB], dwr2[RB];
    #pragma unroll
    for (int k = 0; k < RB; k++) {
        dwr0[k] = dw[k * 384 + t];
        dwr1[k] = dw[k * 384 + t + 128];
        dwr2[k] = dw[k * 384 + t + 256];
    }
    float db0 = db[t], db1 = db[t + 128], db2 = db[t + 256];

    const float* vold = sel ? g_v1 : g_v0;
    float*       vnew = sel ? g_v0 : g_v1;

    int start = g_rowptr[n], end = g_rowptr[n + 1];
    float accs = 0.f, av0 = 0.f, av1 = 0.f, av2 = 0.f;

    for (int i = start; i < end; i++) {
        int e = g_perm[i];
        int dst = nbrs[2 * e + 1];
        float env = g_env[e];
        const float4* rb4 = (const float4*)&g_rbf[(size_t)e * RB];
        float4 r0 = rb4[0], r1 = rb4[1], r2 = rb4[2], r3 = rb4[3], r4 = rb4[4];
        float rb[RB] = {r0.x, r0.y, r0.z, r0.w, r1.x, r1.y, r1.z, r1.w,
                        r2.x, r2.y, r2.z, r2.w, r3.x, r3.y, r3.z, r3.w,
                        r4.x, r4.y, r4.z, r4.w};
        float a0 = db0, a1 = db1, a2 = db2;
        #pragma unroll
        for (int k = 0; k < RB; k++) {
            a0 = fmaf(rb[k], dwr0[k], a0);
            a1 = fmaf(rb[k], dwr1[k], a1);
            a2 = fmaf(rb[k], dwr2[k], a2);
        }
        a0 *= env; a1 *= env; a2 *= env;

        const float* ph = g_phi + (size_t)dst * 384;
        float s0 = ph[t] * a0;
        float s1 = ph[t + 128] * a1;
        float s2 = ph[t + 256] * a2;
        accs += s1;

        float ux = g_unit[(size_t)e * 3 + 0];
        float uy = g_unit[(size_t)e * 3 + 1];
        float uz = g_unit[(size_t)e * 3 + 2];
        const float* vo = vold + (size_t)dst * 384 + 3 * t;
        av0 += fmaf(s0, vo[0], s2 * ux);
        av1 += fmaf(s0, vo[1], s2 * uy);
        av2 += fmaf(s0, vo[2], s2 * uz);
    }

    g_s[(size_t)n * 128 + t] += accs;
    const float* vs = vold + (size_t)n * 384 + 3 * t;
    float*       vp = vnew + (size_t)n * 384 + 3 * t;
    vp[0] = vs[0] + av0;
    vp[1] = vs[1] + av1;
    vp[2] = vs[2] + av2;
}

// ---------------- update stage 1 ----------------
constexpr int TA = 8;
__global__ void __launch_bounds__(128)
upd1_kernel(const float* __restrict__ U, const float* __restrict__ Vw, int sel) {
    __shared__ __align__(16) float v_s[TA * 384];
    int t = threadIdx.x;
    int n0 = blockIdx.x * TA;
    const float* vcur = sel ? g_v1 : g_v0;

    for (int i = t; i < TA * 384; i += 128) {
        size_t gi = (size_t)n0 * 384 + i;
        v_s[i] = (gi < (size_t)NN * 384) ? vcur[gi] : 0.f;
    }
    __syncthreads();

    float uv[TA][3], vv[TA][3];
    #pragma unroll
    for (int a = 0; a < TA; a++)
        #pragma unroll
        for (int d = 0; d < 3; d++) { uv[a][d] = 0.f; vv[a][d] = 0.f; }

    for (int f4 = 0; f4 < 32; f4++) {
        float u0 = U[(f4 * 4 + 0) * 128 + t];
        float u1 = U[(f4 * 4 + 1) * 128 + t];
        float u2 = U[(f4 * 4 + 2) * 128 + t];
        float u3 = U[(f4 * 4 + 3) * 128 + t];
        float w0 = Vw[(f4 * 4 + 0) * 128 + t];
        float w1 = Vw[(f4 * 4 + 1) * 128 + t];
        float w2 = Vw[(f4 * 4 + 2) * 128 + t];
        float w3 = Vw[(f4 * 4 + 3) * 128 + t];
        #pragma unroll
        for (int a = 0; a < TA; a++) {
            const float4* vp = reinterpret_cast<const float4*>(&v_s[a * 384 + f4 * 12]);
            float4 p0 = vp[0], p1 = vp[1], p2 = vp[2];
            uv[a][0] = fmaf(p0.x, u0, fmaf(p0.w, u1, fmaf(p1.z, u2, fmaf(p2.y, u3, uv[a][0]))));
            uv[a][1] = fmaf(p0.y, u0, fmaf(p1.x, u1, fmaf(p1.w, u2, fmaf(p2.z, u3, uv[a][1]))));
            uv[a][2] = fmaf(p0.z, u0, fmaf(p1.y, u1, fmaf(p2.x, u2, fmaf(p2.w, u3, uv[a][2]))));
            vv[a][0] = fmaf(p0.x, w0, fmaf(p0.w, w1, fmaf(p1.z, w2, fmaf(p2.y, w3, vv[a][0]))));
            vv[a][1] = fmaf(p0.y, w0, fmaf(p1.x, w1, fmaf(p1.w, w2, fmaf(p2.z, w3, vv[a][1]))));
            vv[a][2] = fmaf(p0.z, w0, fmaf(p1.y, w1, fmaf(p2.x, w2, fmaf(p2.w, w3, vv[a][2]))));
        }
    }

    #pragma unroll
    for (int a = 0; a < TA; a++) {
        int n = n0 + a;
        if (n >= NN) break;
        float dt = uv[a][0] * vv[a][0] + uv[a][1] * vv[a][1] + uv[a][2] * vv[a][2];
        float vn = sqrtf(vv[a][0] * vv[a][0] + vv[a][1] * vv[a][1] + vv[a][2] * vv[a][2] + EPS3);
        g_uv[(size_t)n * 384 + 3 * t + 0] = uv[a][0];
        g_uv[(size_t)n * 384 + 3 * t + 1] = uv[a][1];
        g_uv[(size_t)n * 384 + 3 * t + 2] = uv[a][2];
        g_dot[(size_t)n * 128 + t] = dt;
        g_stk[(size_t)n * 256 + t] = g_s[(size_t)n * 128 + t];
        g_stk[(size_t)n * 256 + 128 + t] = vn;
    }
}

// ---------------- update apply ----------------
__global__ void apply_kernel(int sel) {
    int i = blockIdx.x * blockDim.x + threadIdx.x;
    if (i >= NN * 128) return;
    int n = i >> 7, g = i & 127;
    float avv = g_spl[(size_t)n * 384 + g];
    float asv = g_spl[(size_t)n * 384 + 128 + g];
    float ass = g_spl[(size_t)n * 384 + 256 + g];
    float* v = (sel ? g_v1 : g_v0) + (size_t)n * 384 + 3 * g;
    const float* uv = g_uv + (size_t)n * 384 + 3 * g;
    v[0] += uv[0] * avv;
    v[1] += uv[1] * avv;
    v[2] += uv[2] * avv;
    g_s[i] += g_dot[i] * asv + ass;
}

// ================ HMMA fused readout ================
constexpr int HP2 = 136;
__global__ void __launch_bounds__(256)
readout_mma(const __half* __restrict__ W1h, const __half* __restrict__ W1l,
            const float* __restrict__ b1, const float* __restrict__ w2,
            const float* __restrict__ b2, const int* __restrict__ nbrs,
            float* __restrict__ out) {
    extern __shared__ __align__(16) __half hsm[];
    __half* Ah = hsm;
    __half* Al = Ah + 128 * HP2;
    __half* Bh = Al + 128 * HP2;
    __half* Bl = Bh + 128 * HP2;
    __shared__ float red[128][2];

    int tid = threadIdx.x;
    int wid = tid >> 5, lane = tid & 31;
    int g = lane >> 2, tq = lane & 3;
    int m0 = (wid & 3) * 32;
    int n0w = (wid >> 2) * 64;
    int nw = wid >> 2;
    int e0 = blockIdx.x * 128;

    for (int idx = tid; idx < 128 * 32; idx += 256) {
        int e = idx >> 5, k = (idx & 31) * 4;
        float4 a = *(const float4*)&g_eij[(size_t)(e0 + e) * 128 + k];
        float x[4] = {a.x, a.y, a.z, a.w};
        #pragma unroll
        for (int j = 0; j < 4; j++) {
            __half hi, lo;
            split_h(x[j], hi, lo);
            Ah[e * HP2 + k + j] = hi;
            Al[e * HP2 + k + j] = lo;
        }
    }

    float rs[2][2] = {{0.f, 0.f}, {0.f, 0.f}};

    for (int nc = 0; nc < 2; nc++) {
        __syncthreads();
        // stage B: straight copy of pre-split [256][128] bank
        for (int idx = tid; idx < 128 * 16; idx += 256) {
            int n = idx >> 4, q8 = (idx & 15) * 8;
            *(uint4*)&Bh[n * HP2 + q8] =
                *(const uint4*)&W1h[(size_t)(nc * 128 + n) * 128 + q8];
            *(uint4*)&Bl[n * HP2 + q8] =
                *(const uint4*)&W1l[(size_t)(nc * 128 + n) * 128 + q8];
        }
        __syncthreads();

        float acc[2][8][4];
        #pragma unroll
        for (int mi = 0; mi < 2; mi++)
            #pragma unroll
            for (int ni = 0; ni < 8; ni++)
                #pragma unroll
                for (int j = 0; j < 4; j++) acc[mi][ni][j] = 0.f;

        #pragma unroll
        for (int ks = 0; ks < 8; ks++) {
            int kl = ks * 16;
            unsigned ah[2][4], al[2][4];
            #pragma unroll
            for (int mi = 0; mi < 2; mi++) {
                int r = m0 + mi * 16;
                ah[mi][0] = *(const unsigned*)&Ah[(r + g) * HP2 + kl + 2 * tq];
                ah[mi][1] = *(const unsigned*)&Ah[(r + g + 8) * HP2 + kl + 2 * tq];
                ah[mi][2] = *(const unsigned*)&Ah[(r + g) * HP2 + kl + 8 + 2 * tq];
                ah[mi][3] = *(const unsigned*)&Ah[(r + g + 8) * HP2 + kl + 8 + 2 * tq];
                al[mi][0] = *(const unsigned*)&Al[(r + g) * HP2 + kl + 2 * tq];
                al[mi][1] = *(const unsigned*)&Al[(r + g + 8) * HP2 + kl + 2 * tq];
                al[mi][2] = *(const unsigned*)&Al[(r + g) * HP2 + kl + 8 + 2 * tq];
                al[mi][3] = *(const unsigned*)&Al[(r + g + 8) * HP2 + kl + 8 + 2 * tq];
            }
            #pragma unroll
            for (int ni = 0; ni < 8; ni++) {
                int n = n0w + ni * 8 + g;
                unsigned bh[2], bl[2];
                bh[0] = *(const unsigned*)&Bh[n * HP2 + kl + 2 * tq];
                bh[1] = *(const unsigned*)&Bh[n * HP2 + kl + 8 + 2 * tq];
                bl[0] = *(const unsigned*)&Bl[n * HP2 + kl + 2 * tq];
                bl[1] = *(const unsigned*)&Bl[n * HP2 + kl + 8 + 2 * tq];
                #pragma unroll
                for (int mi = 0; mi < 2; mi++) {
                    hmma(acc[mi][ni], ah[mi], bh);
                    hmma(acc[mi][ni], ah[mi], bl);
                    hmma(acc[mi][ni], al[mi], bh);
                }
            }
        }

        #pragma unroll
        for (int mi = 0; mi < 2; mi++) {
            #pragma unroll
            for (int ni = 0; ni < 8; ni++) {
                int c = nc * 128 + n0w + ni * 8 + 2 * tq;
                float2 bb = *(const float2*)&b1[c];
                float2 ww = *(const float2*)&w2[c];
                rs[mi][0] += swish(acc[mi][ni][0] + bb.x) * ww.x
                           + swish(acc[mi][ni][1] + bb.y) * ww.y;
                rs[mi][1] += swish(acc[mi][ni][2] + bb.x) * ww.x
                           + swish(acc[mi][ni][3] + bb.y) * ww.y;
            }
        }
    }

    #pragma unroll
    for (int mi = 0; mi < 2; mi++) {
        #pragma unroll
        for (int h = 0; h < 2; h++) {
            float v = rs[mi][h];
            v += __shfl_xor_sync(0xffffffff, v, 1);
            v += __shfl_xor_sync(0xffffffff, v, 2);
            rs[mi][h] = v;
        }
    }
    if (tq == 0) {
        red[m0 + g][nw]          = rs[0][0];
        red[m0 + g + 8][nw]      = rs[0][1];
        red[m0 + 16 + g][nw]     = rs[1][0];
        red[m0 + 16 + g + 8][nw] = rs[1][1];
    }
    __syncthreads();

    if (tid < 128) {
        int e = e0 + tid;
        float s = red[tid][0] + red[tid][1] + b2[0];
        int src = nbrs[2 * e], dst = nbrs[2 * e + 1];
        float fx = s * g_unit[(size_t)e * 3 + 0];
        float fy = s * g_unit[(size_t)e * 3 + 1];
        float fz = s * g_unit[(size_t)e * 3 + 2];
        atomicAdd(&out[src * 3 + 0], fx);
        atomicAdd(&out[src * 3 + 1], fy);
        atomicAdd(&out[src * 3 + 2], fz);
        atomicAdd(&out[dst * 3 + 0], -fx);
        atomicAdd(&out[dst * 3 + 1], -fy);
        atomicAdd(&out[dst * 3 + 2], -fz);
    }
}

// ---------------- host launcher ----------------
extern "C" void kernel_launch(void* const* d_in, const int* in_sizes, int n_in,
                              void* d_out, int out_size) {
    const float* xyz     = (const float*)d_in[0];
    const int*   z       = (const int*)  d_in[1];
    const int*   nbrs    = (const int*)  d_in[2];
    const float* emb     = (const float*)d_in[3];
    const float* de_w    = (const float*)d_in[4];
    const float* de_b    = (const float*)d_in[5];
    const float* msg_w1  = (const float*)d_in[6];
    const float* msg_b1  = (const float*)d_in[7];
    const float* msg_w2  = (const float*)d_in[8];
    const float* msg_b2  = (const float*)d_in[9];
    const float* msg_dw  = (const float*)d_in[10];
    const float* msg_db  = (const float*)d_in[11];
    const float* upd_u   = (const float*)d_in[12];
    const float* upd_v   = (const float*)d_in[13];
    const float* upd_w1  = (const float*)d_in[14];
    const float* upd_b1  = (const float*)d_in[15];
    const float* upd_w2  = (const float*)d_in[16];
    const float* upd_b2  = (const float*)d_in[17];
    const float* edge_w1 = (const float*)d_in[18];
    const float* edge_b1 = (const float*)d_in[19];
    const float* edge_w2 = (const float*)d_in[20];
    const float* edge_b2 = (const float*)d_in[21];
    const float* ro_w1   = (const float*)d_in[22];
    const float* ro_b1   = (const float*)d_in[23];
    const float* ro_w2   = (const float*)d_in[24];
    const float* ro_b2   = (const float*)d_in[25];
    float* out = (float*)d_out;

    float *p_rbf, *p_env, *p_eij, *p_s, *p_phi, *p_stk, *p_spl, *p_t;
    __half *p_wh, *p_wl, *p_h1h, *p_h1l;
    cudaGetSymbolAddress((void**)&p_rbf,  g_rbf);
    cudaGetSymbolAddress((void**)&p_env,  g_env);
    cudaGetSymbolAddress((void**)&p_eij,  g_eij);
    cudaGetSymbolAddress((void**)&p_s,    g_s);
    cudaGetSymbolAddress((void**)&p_phi,  g_phi);
    cudaGetSymbolAddress((void**)&p_stk,  g_stk);
    cudaGetSymbolAddress((void**)&p_spl,  g_spl);
    cudaGetSymbolAddress((void**)&p_t,    g_t);
    cudaGetSymbolAddress((void**)&p_wh,   g_wh);
    cudaGetSymbolAddress((void**)&p_wl,   g_wl);
    cudaGetSymbolAddress((void**)&p_h1h,  g_h1h);
    cudaGetSymbolAddress((void**)&p_h1l,  g_h1l);

    const int SMEM_HM = 4 * 128 * HP * 2;    // 73728
    const int SMEM_RO = 4 * 128 * HP2 * 2;   // 139264
    cudaFuncSetAttribute(hmma_gemm<128, false, true,  false, false, true>,
                         cudaFuncAttributeMaxDynamicSharedMemorySize, SMEM_HM);
    cudaFuncSetAttribute(hmma_gemm<128, false, false, false, true,  false>,
                         cudaFuncAttributeMaxDynamicSharedMemorySize, SMEM_HM);
    cudaFuncSetAttribute(hmma_gemm<256, false, true,  false, false, true>,
                         cudaFuncAttributeMaxDynamicSharedMemorySize, SMEM_HM);
    cudaFuncSetAttribute(hmma_gemm<128, false, false, false, false, false>,
                         cudaFuncAttributeMaxDynamicSharedMemorySize, SMEM_HM);
    cudaFuncSetAttribute(hmma_gemm<256, true,  false, true,  false, false>,
                         cudaFuncAttributeMaxDynamicSharedMemorySize, SMEM_HM);
    cudaFuncSetAttribute(readout_mma,
                         cudaFuncAttributeMaxDynamicSharedMemorySize, SMEM_RO);

    const int gH = (NN + 127) / 128;  // 157
    const int gE = EE / 128;          // 2500

    init_kernel<<<2048, 256>>>(emb, z, out);
    prep_kernel<<<(EE + 255) / 256, 256>>>(xyz, nbrs);

    // weight pre-split (transposed [N][K] half banks)
    dim3 wb(32, 8);
    for (int l = 0; l < 3; l++) {
        wsplit_kernel<<<dim3(128 / 32, 128 / 32), wb>>>(msg_w1 + l * 16384,
            p_wh + OW_MW1 + l * LSTR, p_wl + OW_MW1 + l * LSTR, 128, 128);
        wsplit_kernel<<<dim3(384 / 32, 128 / 32), wb>>>(msg_w2 + l * 49152,
            p_wh + OW_MW2 + l * LSTR, p_wl + OW_MW2 + l * LSTR, 128, 384);
        wsplit_kernel<<<dim3(128 / 32, 256 / 32), wb>>>(upd_w1 + l * 32768,
            p_wh + OW_UW1 + l * LSTR, p_wl + OW_UW1 + l * LSTR, 256, 128);
        wsplit_kernel<<<dim3(384 / 32, 128 / 32), wb>>>(upd_w2 + l * 49152,
            p_wh + OW_UW2 + l * LSTR, p_wl + OW_UW2 + l * LSTR, 128, 384);
        wsplit_kernel<<<dim3(256 / 32, 128 / 32), wb>>>(edge_w1 + l * 32768,
            p_wh + OW_EW1 + l * LSTR, p_wl + OW_EW1 + l * LSTR, 128, 256);
        wsplit_kernel<<<dim3(128 / 32, 256 / 32), wb>>>(edge_w2 + l * 32768,
            p_wh + OW_EW2 + l * LSTR, p_wl + OW_EW2 + l * LSTR, 256, 128);
    }
    wsplit_kernel<<<dim3(256 / 32, 128 / 32), wb>>>(ro_w1, p_wh + OW_RO, p_wl + OW_RO, 128, 256);

    // CSR build
    zero_rowptr<<<(NN + 256) / 256, 256>>>();
    hist_kernel<<<(EE + 255) / 256, 256>>>(nbrs);
    scan_kernel<<<1, 1024>>>();
    cursor_init<<<(NN + 255) / 256, 256>>>();
    scatter_kernel<<<(EE + 255) / 256, 256>>>(nbrs);

    // e_ij = (rbf @ de_w + de_b) * env
    mlp_gemm_small<RB, 128><<<(EE + 31) / 32, 128>>>(p_rbf, de_w, de_b, p_eij, p_env, EE);

    for (int l = 0; l < 3; l++) {
        int sel = l & 1;
        int cur = sel ^ 1;
        const __half* whl = p_wh + l * LSTR;
        const __half* wll = p_wl + l * LSTR;

        // phi = swish(s @ msg_w1 + b1) @ msg_w2 + b2
        hmma_gemm<128, false, true, false, false, true><<<dim3(gH, 1), 256, SMEM_HM>>>(
            p_s, nullptr, nullptr, whl + OW_MW1, wll + OW_MW1, 128,
            msg_b1 + l * 128, 1.f, nullptr, p_h1h, p_h1l, nullptr, NN);
        hmma_gemm<128, false, false, false, true, false><<<dim3(gH, 3), 256, SMEM_HM>>>(
            nullptr, p_h1h, p_h1l, whl + OW_MW2, wll + OW_MW2, 384,
            msg_b2 + l * 384, 1.f, p_phi, nullptr, nullptr, nullptr, NN);

        // CSR message pass
        msg2_kernel<<<NN, 128>>>(nbrs, msg_dw + l * RB * 384, msg_db + l * 384, sel);

        // update block
        upd1_kernel<<<(NN + TA - 1) / TA, 128>>>(upd_u + l * 128 * 128,
                                                 upd_v + l * 128 * 128, cur);
        hmma_gemm<256, false, true, false, false, true><<<dim3(gH, 1), 256, SMEM_HM>>>(
            p_stk, nullptr, nullptr, whl + OW_UW1, wll + OW_UW1, 128,
            upd_b1 + l * 128, 1.f, nullptr, p_h1h, p_h1l, nullptr, NN);
        hmma_gemm<128, false, false, false, true, false><<<dim3(gH, 3), 256, SMEM_HM>>>(
            nullptr, p_h1h, p_h1l, whl + OW_UW2, wll + OW_UW2, 384,
            upd_b2 + l * 384, 1.f, p_spl, nullptr, nullptr, nullptr, NN);
        apply_kernel<<<(NN * 128 + 255) / 256, 256>>>(cur);

        // edge MLP (factored)
        hmma_gemm<128, false, false, false, false, false><<<dim3(gH, 2), 256, SMEM_HM>>>(
            p_s, nullptr, nullptr, whl + OW_EW1, wll + OW_EW1, 256,
            edge_b1 + l * 256, 0.5f, p_t, nullptr, nullptr, nullptr, NN);
        hmma_gemm<256, true, false, true, false, false><<<dim3(gE, 1), 256, SMEM_HM>>>(
            p_t, nullptr, nullptr, whl + OW_EW2, wll + OW_EW2, 128,
            edge_b2 + l * 128, 1.f, p_eij, nullptr, nullptr, nbrs, EE);
    }

    // fused HMMA readout
    readout_mma<<<gE, 256, SMEM_RO>>>(p_wh + OW_RO, p_wl + OW_RO,
                                      ro_b1, ro_w2, ro_b2, nbrs, out);

    (void)in_sizes; (void)n_in; (void)out_size;
}

// round 7
// speedup vs baseline: 1.0426x; 1.0426x over previous
#include <cuda_runtime.h>
#include <cuda_fp16.h>
#include <math.h>

// ---------------- problem constants ----------------
constexpr int NN = 20000;
constexpr int EE = 320000;
constexpr int RB = 20;    // NRBF
constexpr float PI_F = 3.14159265358979323846f;
constexpr float EPS3 = 3e-15f;

// pre-split bank (transposed [N][K]): edge_w2 per layer (128n x 256k), ro_w1 (256n x 128k)
constexpr int OW_EW2 = 0;        // + l*32768
constexpr int OW_RO  = 98304;
constexpr int WTOT   = 131072;

// ---------------- device scratch ----------------
__device__ float g_rbf [(size_t)EE * RB];
__device__ float g_env [EE];
__device__ float g_unit[(size_t)EE * 3];
__device__ float g_eij [(size_t)EE * 128];
__device__ float g_s   [(size_t)NN * 128];
__device__ float g_v0  [(size_t)NN * 384];
__device__ float g_v1  [(size_t)NN * 384];
__device__ float g_phi [(size_t)NN * 384];
__device__ float g_h1  [(size_t)NN * 128];
__device__ float g_uv  [(size_t)NN * 384];
__device__ float g_dot [(size_t)NN * 128];
__device__ float g_stk [(size_t)NN * 256];
__device__ float g_spl [(size_t)NN * 384];
__device__ float g_t   [(size_t)NN * 256];
__device__ __half g_wh [WTOT];
__device__ __half g_wl [WTOT];
// CSR by src
__device__ int g_rowptr[NN + 1];
__device__ int g_cursor[NN];
__device__ int g_perm  [EE];

__device__ __forceinline__ float swish(float x) {
    return x / (1.f + expf(-x));
}

__device__ __forceinline__ void split_h(float x, __half& hi, __half& lo) {
    hi = __float2half_rn(x);
    lo = __float2half_rn(x - __half2float(hi));
}

__device__ __forceinline__ void hmma(float* d, const unsigned* a, const unsigned* b) {
    asm volatile(
        "mma.sync.aligned.m16n8k16.row.col.f32.f16.f16.f32 "
        "{%0,%1,%2,%3}, {%4,%5,%6,%7}, {%8,%9}, {%0,%1,%2,%3};"
        : "+f"(d[0]), "+f"(d[1]), "+f"(d[2]), "+f"(d[3])
        : "r"(a[0]), "r"(a[1]), "r"(a[2]), "r"(a[3]), "r"(b[0]), "r"(b[1]));
}

// ---------------- weight transpose + split: W[K][N] -> Dh/Dl [N][K] ----------------
__global__ void wsplit_kernel(const float* __restrict__ W, __half* __restrict__ Dh,
                              __half* __restrict__ Dl, int K, int N) {
    __shared__ float tile[32][33];
    int tx = threadIdx.x, ty = threadIdx.y;
    int n0 = blockIdx.x * 32, k0 = blockIdx.y * 32;
    #pragma unroll
    for (int r = ty; r < 32; r += 8) {
        int k = k0 + r, n = n0 + tx;
        tile[r][tx] = (k < K && n < N) ? W[(size_t)k * N + n] : 0.f;
    }
    __syncthreads();
    #pragma unroll
    for (int r = ty; r < 32; r += 8) {
        int n = n0 + r, k = k0 + tx;
        if (n < N && k < K) {
            __half hi, lo;
            split_h(tile[tx][r], hi, lo);
            Dh[(size_t)n * K + k] = hi;
            Dl[(size_t)n * K + k] = lo;
        }
    }
}

// ---------------- init ----------------
__global__ void init_kernel(const float* __restrict__ emb, const int* __restrict__ z,
                            float* __restrict__ out) {
    int stride = gridDim.x * blockDim.x;
    for (int i = blockIdx.x * blockDim.x + threadIdx.x; i < NN * 384; i += stride) {
        g_v0[i] = 0.f;
        if (i < NN * 128) {
            int n = i >> 7, f = i & 127;
            g_s[i] = emb[z[n] * 128 + f];
        }
        if (i < NN * 3) out[i] = 0.f;
    }
}

// ---------------- CSR build ----------------
__global__ void zero_rowptr() {
    int i = blockIdx.x * blockDim.x + threadIdx.x;
    if (i <= NN) g_rowptr[i] = 0;
}
__global__ void hist_kernel(const int* __restrict__ nbrs) {
    int e = blockIdx.x * blockDim.x + threadIdx.x;
    if (e < EE) atomicAdd(&g_rowptr[nbrs[2 * e] + 1], 1);
}
__global__ void scan_kernel() {
    __shared__ int sm[1024];
    __shared__ int carry;
    int t = threadIdx.x;
    if (t == 0) carry = 0;
    __syncthreads();
    int nch = (NN + 1 + 1023) / 1024;
    for (int c = 0; c < nch; c++) {
        int i = c * 1024 + t;
        int v = (i <= NN) ? g_rowptr[i] : 0;
        sm[t] = v;
        __syncthreads();
        #pragma unroll
        for (int off = 1; off < 1024; off <<= 1) {
            int x = (t >= off) ? sm[t - off] : 0;
            __syncthreads();
            sm[t] += x;
            __syncthreads();
        }
        if (i <= NN) g_rowptr[i] = sm[t] + carry;
        int total = sm[1023];
        __syncthreads();
        if (t == 0) carry += total;
        __syncthreads();
    }
}
__global__ void cursor_init() {
    int i = blockIdx.x * blockDim.x + threadIdx.x;
    if (i < NN) g_cursor[i] = g_rowptr[i];
}
__global__ void scatter_kernel(const int* __restrict__ nbrs) {
    int e = blockIdx.x * blockDim.x + threadIdx.x;
    if (e < EE) {
        int pos = atomicAdd(&g_cursor[nbrs[2 * e]], 1);
        g_perm[pos] = e;
    }
}

// ---------------- per-edge geometry ----------------
__global__ void prep_kernel(const float* __restrict__ xyz, const int* __restrict__ nbrs) {
    int e = blockIdx.x * blockDim.x + threadIdx.x;
    if (e >= EE) return;
    int s = nbrs[2 * e], d = nbrs[2 * e + 1];
    float dx = xyz[d * 3 + 0] - xyz[s * 3 + 0];
    float dy = xyz[d * 3 + 1] - xyz[s * 3 + 1];
    float dz = xyz[d * 3 + 2] - xyz[s * 3 + 2];
    float d2 = dx * dx + dy * dy + dz * dz + EPS3;
    float dist = sqrtf(d2);
    float inv = 1.f / dist;
    g_unit[(size_t)e * 3 + 0] = dx * inv;
    g_unit[(size_t)e * 3 + 1] = dy * inv;
    g_unit[(size_t)e * 3 + 2] = dz * inv;
    float env = (dist < 5.f) ? 0.5f * (cosf(dist * (PI_F / 5.f)) + 1.f) : 0.f;
    g_env[e] = env;
    float base = dist * (PI_F / 5.f);
    #pragma unroll
    for (int k = 1; k <= RB; k++) {
        g_rbf[(size_t)e * RB + (k - 1)] = sinf(base * (float)k) * inv;
    }
}

// ---------------- small-K GEMM (rbf K=20 init of e_ij) ----------------
template<int K, int NC>
__global__ void __launch_bounds__(NC)
mlp_gemm_small(const float* __restrict__ A, const float* __restrict__ W,
               const float* __restrict__ bias, float* __restrict__ C,
               const float* __restrict__ env, int M) {
    constexpr int TM = 32;
    constexpr int PAD = 36;
    __shared__ __align__(16) float As[K * PAD];
    int m0 = blockIdx.x * TM;
    int tid = threadIdx.x;
    for (int i = tid; i < TM * K; i += NC) {
        int r = i / K, c = i - r * K;
        int m = m0 + r;
        As[c * PAD + r] = (m < M) ? A[(size_t)m * K + c] : 0.f;
    }
    __syncthreads();
    float acc[TM];
    #pragma unroll
    for (int r = 0; r < TM; r++) acc[r] = 0.f;
    const float* Wj = W + tid;
    #pragma unroll
    for (int k = 0; k < K; k++) {
        float w = Wj[k * NC];
        const float4* row = reinterpret_cast<const float4*>(&As[k * PAD]);
        #pragma unroll
        for (int r4 = 0; r4 < TM / 4; r4++) {
            float4 a = row[r4];
            acc[r4 * 4 + 0] = fmaf(a.x, w, acc[r4 * 4 + 0]);
            acc[r4 * 4 + 1] = fmaf(a.y, w, acc[r4 * 4 + 1]);
            acc[r4 * 4 + 2] = fmaf(a.z, w, acc[r4 * 4 + 2]);
            acc[r4 * 4 + 3] = fmaf(a.w, w, acc[r4 * 4 + 3]);
        }
    }
    float bj = bias[tid];
    #pragma unroll
    for (int r = 0; r < TM; r++) {
        int m = m0 + r;
        if (m >= M) break;
        C[(size_t)m * NC + tid] = (acc[r] + bj) * env[m];
    }
}

// ================ generic HMMA GEMM (R5 path + optional pre-split B) ================
constexpr int HP = 72;
template<int K, bool GATHER_SWISH, bool SWISH_OUT, bool ACCUM, bool BPRE>
__global__ void __launch_bounds__(256)
hmma_gemm(const float* __restrict__ Ain, const float* __restrict__ W,
          const __half* __restrict__ Wph, const __half* __restrict__ Wpl, int ldw,
          const float* __restrict__ bias, float bias_scale, float* __restrict__ C,
          const int* __restrict__ nbrs, int M) {
    extern __shared__ __align__(16) __half hsm[];
    __half* Ah = hsm;
    __half* Al = Ah + 128 * HP;
    __half* Bh = Al + 128 * HP;
    __half* Bl = Bh + 128 * HP;
    __shared__ int s_src[128], s_dst[128];

    int tid = threadIdx.x;
    int wid = tid >> 5, lane = tid & 31;
    int g = lane >> 2, tq = lane & 3;
    int wm0 = (wid & 3) * 32;
    int n0w = (wid >> 2) * 64;
    int m0b = blockIdx.x * 128;
    int col0 = blockIdx.y * 128;

    if (GATHER_SWISH && tid < 128) {
        int m = m0b + tid;
        s_src[tid] = (m < M) ? nbrs[2 * m] : 0;
        s_dst[tid] = (m < M) ? nbrs[2 * m + 1] : 0;
    }

    float acc[2][8][4];
    #pragma unroll
    for (int mi = 0; mi < 2; mi++)
        #pragma unroll
        for (int ni = 0; ni < 8; ni++)
            #pragma unroll
            for (int j = 0; j < 4; j++) acc[mi][ni][j] = 0.f;

    constexpr int NCH = K / 64;
    for (int kc = 0; kc < NCH; kc++) {
        __syncthreads();
        // ---- stage A chunk [128 rows][64 k] (fp32 in-block split, R5 path) ----
        for (int idx = tid; idx < 128 * 16; idx += 256) {
            int r = idx >> 4, k = (idx & 15) * 4;
            int m = m0b + r;
            float x[4] = {0.f, 0.f, 0.f, 0.f};
            if (m < M) {
                if (GATHER_SWISH) {
                    float4 a = *(const float4*)&Ain[(size_t)s_src[r] * K + kc * 64 + k];
                    float4 b = *(const float4*)&Ain[(size_t)s_dst[r] * K + kc * 64 + k];
                    x[0] = swish(a.x + b.x); x[1] = swish(a.y + b.y);
                    x[2] = swish(a.z + b.z); x[3] = swish(a.w + b.w);
                } else {
                    float4 a = *(const float4*)&Ain[(size_t)m * K + kc * 64 + k];
                    x[0] = a.x; x[1] = a.y; x[2] = a.z; x[3] = a.w;
                }
            }
            #pragma unroll
            for (int j = 0; j < 4; j++) {
                __half hi, lo;
                split_h(x[j], hi, lo);
                Ah[r * HP + k + j] = hi;
                Al[r * HP + k + j] = lo;
            }
        }
        // ---- stage B chunk ----
        if (BPRE) {
            // straight copy from pre-split transposed [N][K] bank
            for (int idx = tid; idx < 128 * 8; idx += 256) {
                int n = idx >> 3, q8 = (idx & 7) * 8;
                *(uint4*)&Bh[n * HP + q8] =
                    *(const uint4*)&Wph[(size_t)(col0 + n) * K + kc * 64 + q8];
                *(uint4*)&Bl[n * HP + q8] =
                    *(const uint4*)&Wpl[(size_t)(col0 + n) * K + kc * 64 + q8];
            }
        } else {
            // R5 path: split fp32 W[k][n] on the fly
            for (int idx = tid; idx < 128 * 16; idx += 256) {
                int n = idx & 127, kl = (idx >> 7) * 4;
                #pragma unroll
                for (int j = 0; j < 4; j++) {
                    float w = W[(size_t)(kc * 64 + kl + j) * ldw + col0 + n];
                    __half hi, lo;
                    split_h(w, hi, lo);
                    Bh[n * HP + kl + j] = hi;
                    Bl[n * HP + kl + j] = lo;
                }
            }
        }
        __syncthreads();

        #pragma unroll
        for (int ks = 0; ks < 4; ks++) {
            int kl = ks * 16;
            unsigned ah[2][4], al[2][4];
            #pragma unroll
            for (int mi = 0; mi < 2; mi++) {
                int r = wm0 + mi * 16;
                ah[mi][0] = *(const unsigned*)&Ah[(r + g) * HP + kl + 2 * tq];
                ah[mi][1] = *(const unsigned*)&Ah[(r + g + 8) * HP + kl + 2 * tq];
                ah[mi][2] = *(const unsigned*)&Ah[(r + g) * HP + kl + 8 + 2 * tq];
                ah[mi][3] = *(const unsigned*)&Ah[(r + g + 8) * HP + kl + 8 + 2 * tq];
                al[mi][0] = *(const unsigned*)&Al[(r + g) * HP + kl + 2 * tq];
                al[mi][1] = *(const unsigned*)&Al[(r + g + 8) * HP + kl + 2 * tq];
                al[mi][2] = *(const unsigned*)&Al[(r + g) * HP + kl + 8 + 2 * tq];
                al[mi][3] = *(const unsigned*)&Al[(r + g + 8) * HP + kl + 8 + 2 * tq];
            }
            #pragma unroll
            for (int ni = 0; ni < 8; ni++) {
                int n = n0w + ni * 8 + g;
                unsigned bh[2], bl[2];
                bh[0] = *(const unsigned*)&Bh[n * HP + kl + 2 * tq];
                bh[1] = *(const unsigned*)&Bh[n * HP + kl + 8 + 2 * tq];
                bl[0] = *(const unsigned*)&Bl[n * HP + kl + 2 * tq];
                bl[1] = *(const unsigned*)&Bl[n * HP + kl + 8 + 2 * tq];
                #pragma unroll
                for (int mi = 0; mi < 2; mi++) {
                    hmma(acc[mi][ni], ah[mi], bh);
                    hmma(acc[mi][ni], ah[mi], bl);
                    hmma(acc[mi][ni], al[mi], bh);
                }
            }
        }
    }

    // ---- epilogue ----
    #pragma unroll
    for (int mi = 0; mi < 2; mi++) {
        #pragma unroll
        for (int ni = 0; ni < 8; ni++) {
            int col = n0w + ni * 8 + 2 * tq;
            float2 bb = *(const float2*)&bias[col0 + col];
            bb.x *= bias_scale; bb.y *= bias_scale;
            #pragma unroll
            for (int h = 0; h < 2; h++) {
                int m = m0b + wm0 + mi * 16 + g + h * 8;
                if (m >= M) continue;
                float2 o;
                o.x = acc[mi][ni][2 * h + 0] + bb.x;
                o.y = acc[mi][ni][2 * h + 1] + bb.y;
                if (SWISH_OUT) { o.x = swish(o.x); o.y = swish(o.y); }
                size_t ci = (size_t)m * ldw + col0 + col;
                if (ACCUM) {
                    float2 old = *(const float2*)&C[ci];
                    o.x += old.x; o.y += old.y;
                }
                *(float2*)&C[ci] = o;
            }
        }
    }
}

// ---------------- CSR message pass ----------------
__global__ void __launch_bounds__(128)
msg2_kernel(const int* __restrict__ nbrs, const float* __restrict__ dw,
            const float* __restrict__ db, int sel) {
    int n = blockIdx.x;
    int t = threadIdx.x;

    float dwr0[RB], dwr1[RB], dwr2[RB];
    #pragma unroll
    for (int k = 0; k < RB; k++) {
        dwr0[k] = dw[k * 384 + t];
        dwr1[k] = dw[k * 384 + t + 128];
        dwr2[k] = dw[k * 384 + t + 256];
    }
    float db0 = db[t], db1 = db[t + 128], db2 = db[t + 256];

    const float* vold = sel ? g_v1 : g_v0;
    float*       vnew = sel ? g_v0 : g_v1;

    int start = g_rowptr[n], end = g_rowptr[n + 1];
    float accs = 0.f, av0 = 0.f, av1 = 0.f, av2 = 0.f;

    for (int i = start; i < end; i++) {
        int e = g_perm[i];
        int dst = nbrs[2 * e + 1];
        float env = g_env[e];
        const float4* rb4 = (const float4*)&g_rbf[(size_t)e * RB];
        float4 r0 = rb4[0], r1 = rb4[1], r2 = rb4[2], r3 = rb4[3], r4 = rb4[4];
        float rb[RB] = {r0.x, r0.y, r0.z, r0.w, r1.x, r1.y, r1.z, r1.w,
                        r2.x, r2.y, r2.z, r2.w, r3.x, r3.y, r3.z, r3.w,
                        r4.x, r4.y, r4.z, r4.w};
        float a0 = db0, a1 = db1, a2 = db2;
        #pragma unroll
        for (int k = 0; k < RB; k++) {
            a0 = fmaf(rb[k], dwr0[k], a0);
            a1 = fmaf(rb[k], dwr1[k], a1);
            a2 = fmaf(rb[k], dwr2[k], a2);
        }
        a0 *= env; a1 *= env; a2 *= env;

        const float* ph = g_phi + (size_t)dst * 384;
        float s0 = ph[t] * a0;
        float s1 = ph[t + 128] * a1;
        float s2 = ph[t + 256] * a2;
        accs += s1;

        float ux = g_unit[(size_t)e * 3 + 0];
        float uy = g_unit[(size_t)e * 3 + 1];
        float uz = g_unit[(size_t)e * 3 + 2];
        const float* vo = vold + (size_t)dst * 384 + 3 * t;
        av0 += fmaf(s0, vo[0], s2 * ux);
        av1 += fmaf(s0, vo[1], s2 * uy);
        av2 += fmaf(s0, vo[2], s2 * uz);
    }

    g_s[(size_t)n * 128 + t] += accs;
    const float* vs = vold + (size_t)n * 384 + 3 * t;
    float*       vp = vnew + (size_t)n * 384 + 3 * t;
    vp[0] = vs[0] + av0;
    vp[1] = vs[1] + av1;
    vp[2] = vs[2] + av2;
}

// ---------------- update stage 1 ----------------
constexpr int TA = 8;
__global__ void __launch_bounds__(128)
upd1_kernel(const float* __restrict__ U, const float* __restrict__ Vw, int sel) {
    __shared__ __align__(16) float v_s[TA * 384];
    int t = threadIdx.x;
    int n0 = blockIdx.x * TA;
    const float* vcur = sel ? g_v1 : g_v0;

    for (int i = t; i < TA * 384; i += 128) {
        size_t gi = (size_t)n0 * 384 + i;
        v_s[i] = (gi < (size_t)NN * 384) ? vcur[gi] : 0.f;
    }
    __syncthreads();

    float uv[TA][3], vv[TA][3];
    #pragma unroll
    for (int a = 0; a < TA; a++)
        #pragma unroll
        for (int d = 0; d < 3; d++) { uv[a][d] = 0.f; vv[a][d] = 0.f; }

    for (int f4 = 0; f4 < 32; f4++) {
        float u0 = U[(f4 * 4 + 0) * 128 + t];
        float u1 = U[(f4 * 4 + 1) * 128 + t];
        float u2 = U[(f4 * 4 + 2) * 128 + t];
        float u3 = U[(f4 * 4 + 3) * 128 + t];
        float w0 = Vw[(f4 * 4 + 0) * 128 + t];
        float w1 = Vw[(f4 * 4 + 1) * 128 + t];
        float w2 = Vw[(f4 * 4 + 2) * 128 + t];
        float w3 = Vw[(f4 * 4 + 3) * 128 + t];
        #pragma unroll
        for (int a = 0; a < TA; a++) {
            const float4* vp = reinterpret_cast<const float4*>(&v_s[a * 384 + f4 * 12]);
            float4 p0 = vp[0], p1 = vp[1], p2 = vp[2];
            uv[a][0] = fmaf(p0.x, u0, fmaf(p0.w, u1, fmaf(p1.z, u2, fmaf(p2.y, u3, uv[a][0]))));
            uv[a][1] = fmaf(p0.y, u0, fmaf(p1.x, u1, fmaf(p1.w, u2, fmaf(p2.z, u3, uv[a][1]))));
            uv[a][2] = fmaf(p0.z, u0, fmaf(p1.y, u1, fmaf(p2.x, u2, fmaf(p2.w, u3, uv[a][2]))));
            vv[a][0] = fmaf(p0.x, w0, fmaf(p0.w, w1, fmaf(p1.z, w2, fmaf(p2.y, w3, vv[a][0]))));
            vv[a][1] = fmaf(p0.y, w0, fmaf(p1.x, w1, fmaf(p1.w, w2, fmaf(p2.z, w3, vv[a][1]))));
            vv[a][2] = fmaf(p0.z, w0, fmaf(p1.y, w1, fmaf(p2.x, w2, fmaf(p2.w, w3, vv[a][2]))));
        }
    }

    #pragma unroll
    for (int a = 0; a < TA; a++) {
        int n = n0 + a;
        if (n >= NN) break;
        float dt = uv[a][0] * vv[a][0] + uv[a][1] * vv[a][1] + uv[a][2] * vv[a][2];
        float vn = sqrtf(vv[a][0] * vv[a][0] + vv[a][1] * vv[a][1] + vv[a][2] * vv[a][2] + EPS3);
        g_uv[(size_t)n * 384 + 3 * t + 0] = uv[a][0];
        g_uv[(size_t)n * 384 + 3 * t + 1] = uv[a][1];
        g_uv[(size_t)n * 384 + 3 * t + 2] = uv[a][2];
        g_dot[(size_t)n * 128 + t] = dt;
        g_stk[(size_t)n * 256 + t] = g_s[(size_t)n * 128 + t];
        g_stk[(size_t)n * 256 + 128 + t] = vn;
    }
}

// ---------------- update apply ----------------
__global__ void apply_kernel(int sel) {
    int i = blockIdx.x * blockDim.x + threadIdx.x;
    if (i >= NN * 128) return;
    int n = i >> 7, g = i & 127;
    float avv = g_spl[(size_t)n * 384 + g];
    float asv = g_spl[(size_t)n * 384 + 128 + g];
    float ass = g_spl[(size_t)n * 384 + 256 + g];
    float* v = (sel ? g_v1 : g_v0) + (size_t)n * 384 + 3 * g;
    const float* uv = g_uv + (size_t)n * 384 + 3 * g;
    v[0] += uv[0] * avv;
    v[1] += uv[1] * avv;
    v[2] += uv[2] * avv;
    g_s[i] += g_dot[i] * asv + ass;
}

// ================ HMMA fused readout (pre-split B) ================
constexpr int HP2 = 136;
__global__ void __launch_bounds__(256)
readout_mma(const __half* __restrict__ W1h, const __half* __restrict__ W1l,
            const float* __restrict__ b1, const float* __restrict__ w2,
            const float* __restrict__ b2, const int* __restrict__ nbrs,
            float* __restrict__ out) {
    extern __shared__ __align__(16) __half hsm[];
    __half* Ah = hsm;
    __half* Al = Ah + 128 * HP2;
    __half* Bh = Al + 128 * HP2;
    __half* Bl = Bh + 128 * HP2;
    __shared__ float red[128][2];

    int tid = threadIdx.x;
    int wid = tid >> 5, lane = tid & 31;
    int g = lane >> 2, tq = lane & 3;
    int m0 = (wid & 3) * 32;
    int n0w = (wid >> 2) * 64;
    int nw = wid >> 2;
    int e0 = blockIdx.x * 128;

    for (int idx = tid; idx < 128 * 32; idx += 256) {
        int e = idx >> 5, k = (idx & 31) * 4;
        float4 a = *(const float4*)&g_eij[(size_t)(e0 + e) * 128 + k];
        float x[4] = {a.x, a.y, a.z, a.w};
        #pragma unroll
        for (int j = 0; j < 4; j++) {
            __half hi, lo;
            split_h(x[j], hi, lo);
            Ah[e * HP2 + k + j] = hi;
            Al[e * HP2 + k + j] = lo;
        }
    }

    float rs[2][2] = {{0.f, 0.f}, {0.f, 0.f}};

    for (int nc = 0; nc < 2; nc++) {
        __syncthreads();
        for (int idx = tid; idx < 128 * 16; idx += 256) {
            int n = idx >> 4, q8 = (idx & 15) * 8;
            *(uint4*)&Bh[n * HP2 + q8] =
                *(const uint4*)&W1h[(size_t)(nc * 128 + n) * 128 + q8];
            *(uint4*)&Bl[n * HP2 + q8] =
                *(const uint4*)&W1l[(size_t)(nc * 128 + n) * 128 + q8];
        }
        __syncthreads();

        float acc[2][8][4];
        #pragma unroll
        for (int mi = 0; mi < 2; mi++)
            #pragma unroll
            for (int ni = 0; ni < 8; ni++)
                #pragma unroll
                for (int j = 0; j < 4; j++) acc[mi][ni][j] = 0.f;

        #pragma unroll
        for (int ks = 0; ks < 8; ks++) {
            int kl = ks * 16;
            unsigned ah[2][4], al[2][4];
            #pragma unroll
            for (int mi = 0; mi < 2; mi++) {
                int r = m0 + mi * 16;
                ah[mi][0] = *(const unsigned*)&Ah[(r + g) * HP2 + kl + 2 * tq];
                ah[mi][1] = *(const unsigned*)&Ah[(r + g + 8) * HP2 + kl + 2 * tq];
                ah[mi][2] = *(const unsigned*)&Ah[(r + g) * HP2 + kl + 8 + 2 * tq];
                ah[mi][3] = *(const unsigned*)&Ah[(r + g + 8) * HP2 + kl + 8 + 2 * tq];
                al[mi][0] = *(const unsigned*)&Al[(r + g) * HP2 + kl + 2 * tq];
                al[mi][1] = *(const unsigned*)&Al[(r + g + 8) * HP2 + kl + 2 * tq];
                al[mi][2] = *(const unsigned*)&Al[(r + g) * HP2 + kl + 8 + 2 * tq];
                al[mi][3] = *(const unsigned*)&Al[(r + g + 8) * HP2 + kl + 8 + 2 * tq];
            }
            #pragma unroll
            for (int ni = 0; ni < 8; ni++) {
                int n = n0w + ni * 8 + g;
                unsigned bh[2], bl[2];
                bh[0] = *(const unsigned*)&Bh[n * HP2 + kl + 2 * tq];
                bh[1] = *(const unsigned*)&Bh[n * HP2 + kl + 8 + 2 * tq];
                bl[0] = *(const unsigned*)&Bl[n * HP2 + kl + 2 * tq];
                bl[1] = *(const unsigned*)&Bl[n * HP2 + kl + 8 + 2 * tq];
                #pragma unroll
                for (int mi = 0; mi < 2; mi++) {
                    hmma(acc[mi][ni], ah[mi], bh);
                    hmma(acc[mi][ni], ah[mi], bl);
                    hmma(acc[mi][ni], al[mi], bh);
                }
            }
        }

        #pragma unroll
        for (int mi = 0; mi < 2; mi++) {
            #pragma unroll
            for (int ni = 0; ni < 8; ni++) {
                int c = nc * 128 + n0w + ni * 8 + 2 * tq;
                float2 bb = *(const float2*)&b1[c];
                float2 ww = *(const float2*)&w2[c];
                rs[mi][0] += swish(acc[mi][ni][0] + bb.x) * ww.x
                           + swish(acc[mi][ni][1] + bb.y) * ww.y;
                rs[mi][1] += swish(acc[mi][ni][2] + bb.x) * ww.x
                           + swish(acc[mi][ni][3] + bb.y) * ww.y;
            }
        }
    }

    #pragma unroll
    for (int mi = 0; mi < 2; mi++) {
        #pragma unroll
        for (int h = 0; h < 2; h++) {
            float v = rs[mi][h];
            v += __shfl_xor_sync(0xffffffff, v, 1);
            v += __shfl_xor_sync(0xffffffff, v, 2);
            rs[mi][h] = v;
        }
    }
    if (tq == 0) {
        red[m0 + g][nw]          = rs[0][0];
        red[m0 + g + 8][nw]      = rs[0][1];
        red[m0 + 16 + g][nw]     = rs[1][0];
        red[m0 + 16 + g + 8][nw] = rs[1][1];
    }
    __syncthreads();

    if (tid < 128) {
        int e = e0 + tid;
        float s = red[tid][0] + red[tid][1] + b2[0];
        int src = nbrs[2 * e], dst = nbrs[2 * e + 1];
        float fx = s * g_unit[(size_t)e * 3 + 0];
        float fy = s * g_unit[(size_t)e * 3 + 1];
        float fz = s * g_unit[(size_t)e * 3 + 2];
        atomicAdd(&out[src * 3 + 0], fx);
        atomicAdd(&out[src * 3 + 1], fy);
        atomicAdd(&out[src * 3 + 2], fz);
        atomicAdd(&out[dst * 3 + 0], -fx);
        atomicAdd(&out[dst * 3 + 1], -fy);
        atomicAdd(&out[dst * 3 + 2], -fz);
    }
}

// ---------------- host launcher ----------------
extern "C" void kernel_launch(void* const* d_in, const int* in_sizes, int n_in,
                              void* d_out, int out_size) {
    const float* xyz     = (const float*)d_in[0];
    const int*   z       = (const int*)  d_in[1];
    const int*   nbrs    = (const int*)  d_in[2];
    const float* emb     = (const float*)d_in[3];
    const float* de_w    = (const float*)d_in[4];
    const float* de_b    = (const float*)d_in[5];
    const float* msg_w1  = (const float*)d_in[6];
    const float* msg_b1  = (const float*)d_in[7];
    const float* msg_w2  = (const float*)d_in[8];
    const float* msg_b2  = (const float*)d_in[9];
    const float* msg_dw  = (const float*)d_in[10];
    const float* msg_db  = (const float*)d_in[11];
    const float* upd_u   = (const float*)d_in[12];
    const float* upd_v   = (const float*)d_in[13];
    const float* upd_w1  = (const float*)d_in[14];
    const float* upd_b1  = (const float*)d_in[15];
    const float* upd_w2  = (const float*)d_in[16];
    const float* upd_b2  = (const float*)d_in[17];
    const float* edge_w1 = (const float*)d_in[18];
    const float* edge_b1 = (const float*)d_in[19];
    const float* edge_w2 = (const float*)d_in[20];
    const float* edge_b2 = (const float*)d_in[21];
    const float* ro_w1   = (const float*)d_in[22];
    const float* ro_b1   = (const float*)d_in[23];
    const float* ro_w2   = (const float*)d_in[24];
    const float* ro_b2   = (const float*)d_in[25];
    float* out = (float*)d_out;

    float *p_rbf, *p_env, *p_eij, *p_s, *p_phi, *p_h1, *p_stk, *p_spl, *p_t;
    __half *p_wh, *p_wl;
    cudaGetSymbolAddress((void**)&p_rbf,  g_rbf);
    cudaGetSymbolAddress((void**)&p_env,  g_env);
    cudaGetSymbolAddress((void**)&p_eij,  g_eij);
    cudaGetSymbolAddress((void**)&p_s,    g_s);
    cudaGetSymbolAddress((void**)&p_phi,  g_phi);
    cudaGetSymbolAddress((void**)&p_h1,   g_h1);
    cudaGetSymbolAddress((void**)&p_stk,  g_stk);
    cudaGetSymbolAddress((void**)&p_spl,  g_spl);
    cudaGetSymbolAddress((void**)&p_t,    g_t);
    cudaGetSymbolAddress((void**)&p_wh,   g_wh);
    cudaGetSymbolAddress((void**)&p_wl,   g_wl);

    const int SMEM_HM = 4 * 128 * HP * 2;    // 73728
    const int SMEM_RO = 4 * 128 * HP2 * 2;   // 139264
    cudaFuncSetAttribute(hmma_gemm<128, false, true,  false, false>,
                         cudaFuncAttributeMaxDynamicSharedMemorySize, SMEM_HM);
    cudaFuncSetAttribute(hmma_gemm<128, false, false, false, false>,
                         cudaFuncAttributeMaxDynamicSharedMemorySize, SMEM_HM);
    cudaFuncSetAttribute(hmma_gemm<256, false, true,  false, false>,
                         cudaFuncAttributeMaxDynamicSharedMemorySize, SMEM_HM);
    cudaFuncSetAttribute(hmma_gemm<256, true,  false, true,  true>,
                         cudaFuncAttributeMaxDynamicSharedMemorySize, SMEM_HM);
    cudaFuncSetAttribute(readout_mma,
                         cudaFuncAttributeMaxDynamicSharedMemorySize, SMEM_RO);

    const int gH = (NN + 127) / 128;  // 157
    const int gE = EE / 128;          // 2500

    init_kernel<<<2048, 256>>>(emb, z, out);
    prep_kernel<<<(EE + 255) / 256, 256>>>(xyz, nbrs);

    // pre-split only the 2500-block consumers' weights: edge_w2 (x3), ro_w1
    dim3 wb(32, 8);
    for (int l = 0; l < 3; l++)
        wsplit_kernel<<<dim3(128 / 32, 256 / 32), wb>>>(edge_w2 + l * 32768,
            p_wh + OW_EW2 + l * 32768, p_wl + OW_EW2 + l * 32768, 256, 128);
    wsplit_kernel<<<dim3(256 / 32, 128 / 32), wb>>>(ro_w1, p_wh + OW_RO, p_wl + OW_RO, 128, 256);

    // CSR build
    zero_rowptr<<<(NN + 256) / 256, 256>>>();
    hist_kernel<<<(EE + 255) / 256, 256>>>(nbrs);
    scan_kernel<<<1, 1024>>>();
    cursor_init<<<(NN + 255) / 256, 256>>>();
    scatter_kernel<<<(EE + 255) / 256, 256>>>(nbrs);

    // e_ij = (rbf @ de_w + de_b) * env
    mlp_gemm_small<RB, 128><<<(EE + 31) / 32, 128>>>(p_rbf, de_w, de_b, p_eij, p_env, EE);

    for (int l = 0; l < 3; l++) {
        int sel = l & 1;
        int cur = sel ^ 1;

        // phi = swish(s @ msg_w1 + b1) @ msg_w2 + b2   (R5 path)
        hmma_gemm<128, false, true, false, false><<<dim3(gH, 1), 256, SMEM_HM>>>(
            p_s, msg_w1 + l * 128 * 128, nullptr, nullptr, 128,
            msg_b1 + l * 128, 1.f, p_h1, nullptr, NN);
        hmma_gemm<128, false, false, false, false><<<dim3(gH, 3), 256, SMEM_HM>>>(
            p_h1, msg_w2 + l * 128 * 384, nullptr, nullptr, 384,
            msg_b2 + l * 384, 1.f, p_phi, nullptr, NN);

        // CSR message pass
        msg2_kernel<<<NN, 128>>>(nbrs, msg_dw + l * RB * 384, msg_db + l * 384, sel);

        // update block (R5 path)
        upd1_kernel<<<(NN + TA - 1) / TA, 128>>>(upd_u + l * 128 * 128,
                                                 upd_v + l * 128 * 128, cur);
        hmma_gemm<256, false, true, false, false><<<dim3(gH, 1), 256, SMEM_HM>>>(
            p_stk, upd_w1 + l * 256 * 128, nullptr, nullptr, 128,
            upd_b1 + l * 128, 1.f, p_h1, nullptr, NN);
        hmma_gemm<128, false, false, false, false><<<dim3(gH, 3), 256, SMEM_HM>>>(
            p_h1, upd_w2 + l * 128 * 384, nullptr, nullptr, 384,
            upd_b2 + l * 384, 1.f, p_spl, nullptr, NN);
        apply_kernel<<<(NN * 128 + 255) / 256, 256>>>(cur);

        // edge MLP: edge1 R5 path; edge2 with PRE-SPLIT B (2500 blocks)
        hmma_gemm<128, false, false, false, false><<<dim3(gH, 2), 256, SMEM_HM>>>(
            p_s, edge_w1 + l * 128 * 256, nullptr, nullptr, 256,
            edge_b1 + l * 256, 0.5f, p_t, nullptr, NN);
        hmma_gemm<256, true, false, true, true><<<dim3(gE, 1), 256, SMEM_HM>>>(
            p_t, nullptr, p_wh + OW_EW2 + l * 32768, p_wl + OW_EW2 + l * 32768, 128,
            edge_b2 + l * 128, 1.f, p_eij, nbrs, EE);
    }

    // fused HMMA readout (pre-split B)
    readout_mma<<<gE, 256, SMEM_RO>>>(p_wh + OW_RO, p_wl + OW_RO,
                                      ro_b1, ro_w2, ro_b2, nbrs, out);

    (void)in_sizes; (void)n_in; (void)out_size;
}

// round 8
// speedup vs baseline: 1.5254x; 1.4630x over previous
#include <cuda_runtime.h>
#include <cuda_fp16.h>
#include <math.h>

// ---------------- problem constants ----------------
constexpr int NN = 20000;
constexpr int EE = 320000;
constexpr int RB = 20;    // NRBF
constexpr float PI_F = 3.14159265358979323846f;
constexpr float EPS3 = 3e-15f;

// ---------------- device scratch ----------------
__device__ float g_rbf [(size_t)EE * RB];
__device__ float g_env [EE];
__device__ float g_unit[(size_t)EE * 3];
__device__ float g_eij [(size_t)EE * 128];
__device__ float g_s   [(size_t)NN * 128];
__device__ float g_v0  [(size_t)NN * 384];
__device__ float g_v1  [(size_t)NN * 384];
__device__ float g_phi [(size_t)NN * 384];
__device__ float g_h1  [(size_t)NN * 128];
__device__ float g_uv  [(size_t)NN * 384];
__device__ float g_dot [(size_t)NN * 128];
__device__ float g_stk [(size_t)NN * 256];
__device__ float g_spl [(size_t)NN * 384];
__device__ float g_t   [(size_t)NN * 256];
// CSR by src
__device__ int g_rowptr[NN + 1];
__device__ int g_cursor[NN];
__device__ int g_perm  [EE];

__device__ __forceinline__ float swish(float x) {
    return x / (1.f + expf(-x));
}

__device__ __forceinline__ void split_h(float x, __half& hi, __half& lo) {
    hi = __float2half_rn(x);
    lo = __float2half_rn(x - __half2float(hi));
}

__device__ __forceinline__ void hmma(float* d, const unsigned* a, const unsigned* b) {
    asm volatile(
        "mma.sync.aligned.m16n8k16.row.col.f32.f16.f16.f32 "
        "{%0,%1,%2,%3}, {%4,%5,%6,%7}, {%8,%9}, {%0,%1,%2,%3};"
        : "+f"(d[0]), "+f"(d[1]), "+f"(d[2]), "+f"(d[3])
        : "r"(a[0]), "r"(a[1]), "r"(a[2]), "r"(a[3]), "r"(b[0]), "r"(b[1]));
}

// ---------------- init ----------------
__global__ void init_kernel(const float* __restrict__ emb, const int* __restrict__ z,
                            float* __restrict__ out) {
    int stride = gridDim.x * blockDim.x;
    for (int i = blockIdx.x * blockDim.x + threadIdx.x; i < NN * 384; i += stride) {
        g_v0[i] = 0.f;
        if (i < NN * 128) {
            int n = i >> 7, f = i & 127;
            g_s[i] = emb[z[n] * 128 + f];
        }
        if (i < NN * 3) out[i] = 0.f;
    }
}

// ---------------- CSR build ----------------
__global__ void zero_rowptr() {
    int i = blockIdx.x * blockDim.x + threadIdx.x;
    if (i <= NN) g_rowptr[i] = 0;
}
__global__ void hist_kernel(const int* __restrict__ nbrs) {
    int e = blockIdx.x * blockDim.x + threadIdx.x;
    if (e < EE) atomicAdd(&g_rowptr[nbrs[2 * e] + 1], 1);
}
__global__ void scan_kernel() {
    __shared__ int sm[1024];
    __shared__ int carry;
    int t = threadIdx.x;
    if (t == 0) carry = 0;
    __syncthreads();
    int nch = (NN + 1 + 1023) / 1024;
    for (int c = 0; c < nch; c++) {
        int i = c * 1024 + t;
        int v = (i <= NN) ? g_rowptr[i] : 0;
        sm[t] = v;
        __syncthreads();
        #pragma unroll
        for (int off = 1; off < 1024; off <<= 1) {
            int x = (t >= off) ? sm[t - off] : 0;
            __syncthreads();
            sm[t] += x;
            __syncthreads();
        }
        if (i <= NN) g_rowptr[i] = sm[t] + carry;
        int total = sm[1023];
        __syncthreads();
        if (t == 0) carry += total;
        __syncthreads();
    }
}
__global__ void cursor_init() {
    int i = blockIdx.x * blockDim.x + threadIdx.x;
    if (i < NN) g_cursor[i] = g_rowptr[i];
}
__global__ void scatter_kernel(const int* __restrict__ nbrs) {
    int e = blockIdx.x * blockDim.x + threadIdx.x;
    if (e < EE) {
        int pos = atomicAdd(&g_cursor[nbrs[2 * e]], 1);
        g_perm[pos] = e;
    }
}

// ---------------- per-edge geometry ----------------
__global__ void prep_kernel(const float* __restrict__ xyz, const int* __restrict__ nbrs) {
    int e = blockIdx.x * blockDim.x + threadIdx.x;
    if (e >= EE) return;
    int s = nbrs[2 * e], d = nbrs[2 * e + 1];
    float dx = xyz[d * 3 + 0] - xyz[s * 3 + 0];
    float dy = xyz[d * 3 + 1] - xyz[s * 3 + 1];
    float dz = xyz[d * 3 + 2] - xyz[s * 3 + 2];
    float d2 = dx * dx + dy * dy + dz * dz + EPS3;
    float dist = sqrtf(d2);
    float inv = 1.f / dist;
    g_unit[(size_t)e * 3 + 0] = dx * inv;
    g_unit[(size_t)e * 3 + 1] = dy * inv;
    g_unit[(size_t)e * 3 + 2] = dz * inv;
    float env = (dist < 5.f) ? 0.5f * (cosf(dist * (PI_F / 5.f)) + 1.f) : 0.f;
    g_env[e] = env;
    float base = dist * (PI_F / 5.f);
    #pragma unroll
    for (int k = 1; k <= RB; k++) {
        g_rbf[(size_t)e * RB + (k - 1)] = sinf(base * (float)k) * inv;
    }
}

// ---------------- small-K GEMM (rbf K=20 init of e_ij) ----------------
template<int K, int NC>
__global__ void __launch_bounds__(NC)
mlp_gemm_small(const float* __restrict__ A, const float* __restrict__ W,
               const float* __restrict__ bias, float* __restrict__ C,
               const float* __restrict__ env, int M) {
    constexpr int TM = 32;
    constexpr int PAD = 36;
    __shared__ __align__(16) float As[K * PAD];
    int m0 = blockIdx.x * TM;
    int tid = threadIdx.x;
    for (int i = tid; i < TM * K; i += NC) {
        int r = i / K, c = i - r * K;
        int m = m0 + r;
        As[c * PAD + r] = (m < M) ? A[(size_t)m * K + c] : 0.f;
    }
    __syncthreads();
    float acc[TM];
    #pragma unroll
    for (int r = 0; r < TM; r++) acc[r] = 0.f;
    const float* Wj = W + tid;
    #pragma unroll
    for (int k = 0; k < K; k++) {
        float w = Wj[k * NC];
        const float4* row = reinterpret_cast<const float4*>(&As[k * PAD]);
        #pragma unroll
        for (int r4 = 0; r4 < TM / 4; r4++) {
            float4 a = row[r4];
            acc[r4 * 4 + 0] = fmaf(a.x, w, acc[r4 * 4 + 0]);
            acc[r4 * 4 + 1] = fmaf(a.y, w, acc[r4 * 4 + 1]);
            acc[r4 * 4 + 2] = fmaf(a.z, w, acc[r4 * 4 + 2]);
            acc[r4 * 4 + 3] = fmaf(a.w, w, acc[r4 * 4 + 3]);
        }
    }
    float bj = bias[tid];
    #pragma unroll
    for (int r = 0; r < TM; r++) {
        int m = m0 + r;
        if (m >= M) break;
        C[(size_t)m * NC + tid] = (acc[r] + bj) * env[m];
    }
}

// ================ generic HMMA GEMM (R5 path) ================
constexpr int HP = 72;
template<int K, bool GATHER_SWISH, bool SWISH_OUT, bool ACCUM>
__global__ void __launch_bounds__(256)
hmma_gemm(const float* __restrict__ Ain, const float* __restrict__ W, int ldw,
          const float* __restrict__ bias, float bias_scale, float* __restrict__ C,
          const int* __restrict__ nbrs, int M) {
    extern __shared__ __align__(16) __half hsm[];
    __half* Ah = hsm;
    __half* Al = Ah + 128 * HP;
    __half* Bh = Al + 128 * HP;
    __half* Bl = Bh + 128 * HP;
    __shared__ int s_src[128], s_dst[128];

    int tid = threadIdx.x;
    int wid = tid >> 5, lane = tid & 31;
    int g = lane >> 2, tq = lane & 3;
    int wm0 = (wid & 3) * 32;
    int n0w = (wid >> 2) * 64;
    int m0b = blockIdx.x * 128;
    int col0 = blockIdx.y * 128;

    if (GATHER_SWISH && tid < 128) {
        int m = m0b + tid;
        s_src[tid] = (m < M) ? nbrs[2 * m] : 0;
        s_dst[tid] = (m < M) ? nbrs[2 * m + 1] : 0;
    }

    float acc[2][8][4];
    #pragma unroll
    for (int mi = 0; mi < 2; mi++)
        #pragma unroll
        for (int ni = 0; ni < 8; ni++)
            #pragma unroll
            for (int j = 0; j < 4; j++) acc[mi][ni][j] = 0.f;

    constexpr int NCH = K / 64;
    for (int kc = 0; kc < NCH; kc++) {
        __syncthreads();
        // ---- stage A chunk [128 rows][64 k] ----
        for (int idx = tid; idx < 128 * 16; idx += 256) {
            int r = idx >> 4, k = (idx & 15) * 4;
            int m = m0b + r;
            float x[4] = {0.f, 0.f, 0.f, 0.f};
            if (m < M) {
                if (GATHER_SWISH) {
                    float4 a = *(const float4*)&Ain[(size_t)s_src[r] * K + kc * 64 + k];
                    float4 b = *(const float4*)&Ain[(size_t)s_dst[r] * K + kc * 64 + k];
                    x[0] = swish(a.x + b.x); x[1] = swish(a.y + b.y);
                    x[2] = swish(a.z + b.z); x[3] = swish(a.w + b.w);
                } else {
                    float4 a = *(const float4*)&Ain[(size_t)m * K + kc * 64 + k];
                    x[0] = a.x; x[1] = a.y; x[2] = a.z; x[3] = a.w;
                }
            }
            #pragma unroll
            for (int j = 0; j < 4; j++) {
                __half hi, lo;
                split_h(x[j], hi, lo);
                Ah[r * HP + k + j] = hi;
                Al[r * HP + k + j] = lo;
            }
        }
        // ---- stage B chunk: split fp32 W[k][n] on the fly ----
        for (int idx = tid; idx < 128 * 16; idx += 256) {
            int n = idx & 127, kl = (idx >> 7) * 4;
            #pragma unroll
            for (int j = 0; j < 4; j++) {
                float w = W[(size_t)(kc * 64 + kl + j) * ldw + col0 + n];
                __half hi, lo;
                split_h(w, hi, lo);
                Bh[n * HP + kl + j] = hi;
                Bl[n * HP + kl + j] = lo;
            }
        }
        __syncthreads();

        #pragma unroll
        for (int ks = 0; ks < 4; ks++) {
            int kl = ks * 16;
            unsigned ah[2][4], al[2][4];
            #pragma unroll
            for (int mi = 0; mi < 2; mi++) {
                int r = wm0 + mi * 16;
                ah[mi][0] = *(const unsigned*)&Ah[(r + g) * HP + kl + 2 * tq];
                ah[mi][1] = *(const unsigned*)&Ah[(r + g + 8) * HP + kl + 2 * tq];
                ah[mi][2] = *(const unsigned*)&Ah[(r + g) * HP + kl + 8 + 2 * tq];
                ah[mi][3] = *(const unsigned*)&Ah[(r + g + 8) * HP + kl + 8 + 2 * tq];
                al[mi][0] = *(const unsigned*)&Al[(r + g) * HP + kl + 2 * tq];
                al[mi][1] = *(const unsigned*)&Al[(r + g + 8) * HP + kl + 2 * tq];
                al[mi][2] = *(const unsigned*)&Al[(r + g) * HP + kl + 8 + 2 * tq];
                al[mi][3] = *(const unsigned*)&Al[(r + g + 8) * HP + kl + 8 + 2 * tq];
            }
            #pragma unroll
            for (int ni = 0; ni < 8; ni++) {
                int n = n0w + ni * 8 + g;
                unsigned bh[2], bl[2];
                bh[0] = *(const unsigned*)&Bh[n * HP + kl + 2 * tq];
                bh[1] = *(const unsigned*)&Bh[n * HP + kl + 8 + 2 * tq];
                bl[0] = *(const unsigned*)&Bl[n * HP + kl + 2 * tq];
                bl[1] = *(const unsigned*)&Bl[n * HP + kl + 8 + 2 * tq];
                #pragma unroll
                for (int mi = 0; mi < 2; mi++) {
                    hmma(acc[mi][ni], ah[mi], bh);
                    hmma(acc[mi][ni], ah[mi], bl);
                    hmma(acc[mi][ni], al[mi], bh);
                }
            }
        }
    }

    // ---- epilogue ----
    #pragma unroll
    for (int mi = 0; mi < 2; mi++) {
        #pragma unroll
        for (int ni = 0; ni < 8; ni++) {
            int col = n0w + ni * 8 + 2 * tq;
            float2 bb = *(const float2*)&bias[col0 + col];
            bb.x *= bias_scale; bb.y *= bias_scale;
            #pragma unroll
            for (int h = 0; h < 2; h++) {
                int m = m0b + wm0 + mi * 16 + g + h * 8;
                if (m >= M) continue;
                float2 o;
                o.x = acc[mi][ni][2 * h + 0] + bb.x;
                o.y = acc[mi][ni][2 * h + 1] + bb.y;
                if (SWISH_OUT) { o.x = swish(o.x); o.y = swish(o.y); }
                size_t ci = (size_t)m * ldw + col0 + col;
                if (ACCUM) {
                    float2 old = *(const float2*)&C[ci];
                    o.x += old.x; o.y += old.y;
                }
                *(float2*)&C[ci] = o;
            }
        }
    }
}

// ---------------- CSR message pass: smem-staged edge metadata ----------------
constexpr int ETILE = 32;
__global__ void __launch_bounds__(128)
msg2_kernel(const int* __restrict__ nbrs, const float* __restrict__ dw,
            const float* __restrict__ db, int sel) {
    __shared__ int   s_dst[ETILE];
    __shared__ float s_env[ETILE];
    __shared__ float s_unit[ETILE][4];
    __shared__ __align__(16) float s_rbf[ETILE][RB];

    int n = blockIdx.x;
    int t = threadIdx.x;

    float dwr0[RB], dwr1[RB], dwr2[RB];
    #pragma unroll
    for (int k = 0; k < RB; k++) {
        dwr0[k] = dw[k * 384 + t];
        dwr1[k] = dw[k * 384 + t + 128];
        dwr2[k] = dw[k * 384 + t + 256];
    }
    float db0 = db[t], db1 = db[t + 128], db2 = db[t + 256];

    const float* vold = sel ? g_v1 : g_v0;
    float*       vnew = sel ? g_v0 : g_v1;

    int start = g_rowptr[n], end = g_rowptr[n + 1];
    float accs = 0.f, av0 = 0.f, av1 = 0.f, av2 = 0.f;

    for (int tile = start; tile < end; tile += ETILE) {
        int m = min(ETILE, end - tile);
        __syncthreads();
        if (t < m) {
            int e = g_perm[tile + t];
            s_dst[t] = nbrs[2 * e + 1];
            s_env[t] = g_env[e];
            s_unit[t][0] = g_unit[(size_t)e * 3 + 0];
            s_unit[t][1] = g_unit[(size_t)e * 3 + 1];
            s_unit[t][2] = g_unit[(size_t)e * 3 + 2];
        }
        // rbf: 5 float4 per edge, cooperative
        for (int idx = t; idx < m * 5; idx += 128) {
            int le = idx / 5, q = idx - le * 5;
            int e = g_perm[tile + le];
            ((float4*)s_rbf[le])[q] = ((const float4*)&g_rbf[(size_t)e * RB])[q];
        }
        __syncthreads();

        for (int le = 0; le < m; le++) {
            const float4* rb4 = (const float4*)s_rbf[le];
            float4 r0 = rb4[0], r1 = rb4[1], r2 = rb4[2], r3 = rb4[3], r4 = rb4[4];
            float rb[RB] = {r0.x, r0.y, r0.z, r0.w, r1.x, r1.y, r1.z, r1.w,
                            r2.x, r2.y, r2.z, r2.w, r3.x, r3.y, r3.z, r3.w,
                            r4.x, r4.y, r4.z, r4.w};
            float a0 = db0, a1 = db1, a2 = db2;
            #pragma unroll
            for (int k = 0; k < RB; k++) {
                a0 = fmaf(rb[k], dwr0[k], a0);
                a1 = fmaf(rb[k], dwr1[k], a1);
                a2 = fmaf(rb[k], dwr2[k], a2);
            }
            float env = s_env[le];
            a0 *= env; a1 *= env; a2 *= env;

            int dst = s_dst[le];
            const float* ph = g_phi + (size_t)dst * 384;
            float s0 = ph[t] * a0;
            float s1 = ph[t + 128] * a1;
            float s2 = ph[t + 256] * a2;
            accs += s1;

            const float* vo = vold + (size_t)dst * 384 + 3 * t;
            av0 += fmaf(s0, vo[0], s2 * s_unit[le][0]);
            av1 += fmaf(s0, vo[1], s2 * s_unit[le][1]);
            av2 += fmaf(s0, vo[2], s2 * s_unit[le][2]);
        }
    }

    g_s[(size_t)n * 128 + t] += accs;
    const float* vs = vold + (size_t)n * 384 + 3 * t;
    float*       vp = vnew + (size_t)n * 384 + 3 * t;
    vp[0] = vs[0] + av0;
    vp[1] = vs[1] + av1;
    vp[2] = vs[2] + av2;
}

// ---------------- update stage 1 ----------------
constexpr int TA = 8;
__global__ void __launch_bounds__(128)
upd1_kernel(const float* __restrict__ U, const float* __restrict__ Vw, int sel) {
    __shared__ __align__(16) float v_s[TA * 384];
    int t = threadIdx.x;
    int n0 = blockIdx.x * TA;
    const float* vcur = sel ? g_v1 : g_v0;

    for (int i = t; i < TA * 384; i += 128) {
        size_t gi = (size_t)n0 * 384 + i;
        v_s[i] = (gi < (size_t)NN * 384) ? vcur[gi] : 0.f;
    }
    __syncthreads();

    float uv[TA][3], vv[TA][3];
    #pragma unroll
    for (int a = 0; a < TA; a++)
        #pragma unroll
        for (int d = 0; d < 3; d++) { uv[a][d] = 0.f; vv[a][d] = 0.f; }

    for (int f4 = 0; f4 < 32; f4++) {
        float u0 = U[(f4 * 4 + 0) * 128 + t];
        float u1 = U[(f4 * 4 + 1) * 128 + t];
        float u2 = U[(f4 * 4 + 2) * 128 + t];
        float u3 = U[(f4 * 4 + 3) * 128 + t];
        float w0 = Vw[(f4 * 4 + 0) * 128 + t];
        float w1 = Vw[(f4 * 4 + 1) * 128 + t];
        float w2 = Vw[(f4 * 4 + 2) * 128 + t];
        float w3 = Vw[(f4 * 4 + 3) * 128 + t];
        #pragma unroll
        for (int a = 0; a < TA; a++) {
            const float4* vp = reinterpret_cast<const float4*>(&v_s[a * 384 + f4 * 12]);
            float4 p0 = vp[0], p1 = vp[1], p2 = vp[2];
            uv[a][0] = fmaf(p0.x, u0, fmaf(p0.w, u1, fmaf(p1.z, u2, fmaf(p2.y, u3, uv[a][0]))));
            uv[a][1] = fmaf(p0.y, u0, fmaf(p1.x, u1, fmaf(p1.w, u2, fmaf(p2.z, u3, uv[a][1]))));
            uv[a][2] = fmaf(p0.z, u0, fmaf(p1.y, u1, fmaf(p2.x, u2, fmaf(p2.w, u3, uv[a][2]))));
            vv[a][0] = fmaf(p0.x, w0, fmaf(p0.w, w1, fmaf(p1.z, w2, fmaf(p2.y, w3, vv[a][0]))));
            vv[a][1] = fmaf(p0.y, w0, fmaf(p1.x, w1, fmaf(p1.w, w2, fmaf(p2.z, w3, vv[a][1]))));
            vv[a][2] = fmaf(p0.z, w0, fmaf(p1.y, w1, fmaf(p2.x, w2, fmaf(p2.w, w3, vv[a][2]))));
        }
    }

    #pragma unroll
    for (int a = 0; a < TA; a++) {
        int n = n0 + a;
        if (n >= NN) break;
        float dt = uv[a][0] * vv[a][0] + uv[a][1] * vv[a][1] + uv[a][2] * vv[a][2];
        float vn = sqrtf(vv[a][0] * vv[a][0] + vv[a][1] * vv[a][1] + vv[a][2] * vv[a][2] + EPS3);
        g_uv[(size_t)n * 384 + 3 * t + 0] = uv[a][0];
        g_uv[(size_t)n * 384 + 3 * t + 1] = uv[a][1];
        g_uv[(size_t)n * 384 + 3 * t + 2] = uv[a][2];
        g_dot[(size_t)n * 128 + t] = dt;
        g_stk[(size_t)n * 256 + t] = g_s[(size_t)n * 128 + t];
        g_stk[(size_t)n * 256 + 128 + t] = vn;
    }
}

// ---------------- update apply ----------------
__global__ void apply_kernel(int sel) {
    int i = blockIdx.x * blockDim.x + threadIdx.x;
    if (i >= NN * 128) return;
    int n = i >> 7, g = i & 127;
    float avv = g_spl[(size_t)n * 384 + g];
    float asv = g_spl[(size_t)n * 384 + 128 + g];
    float ass = g_spl[(size_t)n * 384 + 256 + g];
    float* v = (sel ? g_v1 : g_v0) + (size_t)n * 384 + 3 * g;
    const float* uv = g_uv + (size_t)n * 384 + 3 * g;
    v[0] += uv[0] * avv;
    v[1] += uv[1] * avv;
    v[2] += uv[2] * avv;
    g_s[i] += g_dot[i] * asv + ass;
}

// ================ HMMA fused readout (R5 path) ================
constexpr int HP2 = 136;
__global__ void __launch_bounds__(256)
readout_mma(const float* __restrict__ W1, const float* __restrict__ b1,
            const float* __restrict__ w2, const float* __restrict__ b2,
            const int* __restrict__ nbrs, float* __restrict__ out) {
    extern __shared__ __align__(16) __half hsm[];
    __half* Ah = hsm;
    __half* Al = Ah + 128 * HP2;
    __half* Bh = Al + 128 * HP2;
    __half* Bl = Bh + 128 * HP2;
    __shared__ float red[128][2];

    int tid = threadIdx.x;
    int wid = tid >> 5, lane = tid & 31;
    int g = lane >> 2, tq = lane & 3;
    int m0 = (wid & 3) * 32;
    int n0w = (wid >> 2) * 64;
    int nw = wid >> 2;
    int e0 = blockIdx.x * 128;

    for (int idx = tid; idx < 128 * 32; idx += 256) {
        int e = idx >> 5, k = (idx & 31) * 4;
        float4 a = *(const float4*)&g_eij[(size_t)(e0 + e) * 128 + k];
        float x[4] = {a.x, a.y, a.z, a.w};
        #pragma unroll
        for (int j = 0; j < 4; j++) {
            __half hi, lo;
            split_h(x[j], hi, lo);
            Ah[e * HP2 + k + j] = hi;
            Al[e * HP2 + k + j] = lo;
        }
    }

    float rs[2][2] = {{0.f, 0.f}, {0.f, 0.f}};

    for (int nc = 0; nc < 2; nc++) {
        __syncthreads();
        for (int idx = tid; idx < 128 * 32; idx += 256) {
            int n = idx & 127, k = (idx >> 7) * 4;
            #pragma unroll
            for (int j = 0; j < 4; j++) {
                float w = W1[(size_t)(k + j) * 256 + nc * 128 + n];
                __half hi, lo;
                split_h(w, hi, lo);
                Bh[n * HP2 + k + j] = hi;
                Bl[n * HP2 + k + j] = lo;
            }
        }
        __syncthreads();

        float acc[2][8][4];
        #pragma unroll
        for (int mi = 0; mi < 2; mi++)
            #pragma unroll
            for (int ni = 0; ni < 8; ni++)
                #pragma unroll
                for (int j = 0; j < 4; j++) acc[mi][ni][j] = 0.f;

        #pragma unroll
        for (int ks = 0; ks < 8; ks++) {
            int kl = ks * 16;
            unsigned ah[2][4], al[2][4];
            #pragma unroll
            for (int mi = 0; mi < 2; mi++) {
                int r = m0 + mi * 16;
                ah[mi][0] = *(const unsigned*)&Ah[(r + g) * HP2 + kl + 2 * tq];
                ah[mi][1] = *(const unsigned*)&Ah[(r + g + 8) * HP2 + kl + 2 * tq];
                ah[mi][2] = *(const unsigned*)&Ah[(r + g) * HP2 + kl + 8 + 2 * tq];
                ah[mi][3] = *(const unsigned*)&Ah[(r + g + 8) * HP2 + kl + 8 + 2 * tq];
                al[mi][0] = *(const unsigned*)&Al[(r + g) * HP2 + kl + 2 * tq];
                al[mi][1] = *(const unsigned*)&Al[(r + g + 8) * HP2 + kl + 2 * tq];
                al[mi][2] = *(const unsigned*)&Al[(r + g) * HP2 + kl + 8 + 2 * tq];
                al[mi][3] = *(const unsigned*)&Al[(r + g + 8) * HP2 + kl + 8 + 2 * tq];
            }
            #pragma unroll
            for (int ni = 0; ni < 8; ni++) {
                int n = n0w + ni * 8 + g;
                unsigned bh[2], bl[2];
                bh[0] = *(const unsigned*)&Bh[n * HP2 + kl + 2 * tq];
                bh[1] = *(const unsigned*)&Bh[n * HP2 + kl + 8 + 2 * tq];
                bl[0] = *(const unsigned*)&Bl[n * HP2 + kl + 2 * tq];
                bl[1] = *(const unsigned*)&Bl[n * HP2 + kl + 8 + 2 * tq];
                #pragma unroll
                for (int mi = 0; mi < 2; mi++) {
                    hmma(acc[mi][ni], ah[mi], bh);
                    hmma(acc[mi][ni], ah[mi], bl);
                    hmma(acc[mi][ni], al[mi], bh);
                }
            }
        }

        #pragma unroll
        for (int mi = 0; mi < 2; mi++) {
            #pragma unroll
            for (int ni = 0; ni < 8; ni++) {
                int c = nc * 128 + n0w + ni * 8 + 2 * tq;
                float2 bb = *(const float2*)&b1[c];
                float2 ww = *(const float2*)&w2[c];
                rs[mi][0] += swish(acc[mi][ni][0] + bb.x) * ww.x
                           + swish(acc[mi][ni][1] + bb.y) * ww.y;
                rs[mi][1] += swish(acc[mi][ni][2] + bb.x) * ww.x
                           + swish(acc[mi][ni][3] + bb.y) * ww.y;
            }
        }
    }

    #pragma unroll
    for (int mi = 0; mi < 2; mi++) {
        #pragma unroll
        for (int h = 0; h < 2; h++) {
            float v = rs[mi][h];
            v += __shfl_xor_sync(0xffffffff, v, 1);
            v += __shfl_xor_sync(0xffffffff, v, 2);
            rs[mi][h] = v;
        }
    }
    if (tq == 0) {
        red[m0 + g][nw]          = rs[0][0];
        red[m0 + g + 8][nw]      = rs[0][1];
        red[m0 + 16 + g][nw]     = rs[1][0];
        red[m0 + 16 + g + 8][nw] = rs[1][1];
    }
    __syncthreads();

    if (tid < 128) {
        int e = e0 + tid;
        float s = red[tid][0] + red[tid][1] + b2[0];
        int src = nbrs[2 * e], dst = nbrs[2 * e + 1];
        float fx = s * g_unit[(size_t)e * 3 + 0];
        float fy = s * g_unit[(size_t)e * 3 + 1];
        float fz = s * g_unit[(size_t)e * 3 + 2];
        atomicAdd(&out[src * 3 + 0], fx);
        atomicAdd(&out[src * 3 + 1], fy);
        atomicAdd(&out[src * 3 + 2], fz);
        atomicAdd(&out[dst * 3 + 0], -fx);
        atomicAdd(&out[dst * 3 + 1], -fy);
        atomicAdd(&out[dst * 3 + 2], -fz);
    }
}

// ---------------- host launcher ----------------
extern "C" void kernel_launch(void* const* d_in, const int* in_sizes, int n_in,
                              void* d_out, int out_size) {
    const float* xyz     = (const float*)d_in[0];
    const int*   z       = (const int*)  d_in[1];
    const int*   nbrs    = (const int*)  d_in[2];
    const float* emb     = (const float*)d_in[3];
    const float* de_w    = (const float*)d_in[4];
    const float* de_b    = (const float*)d_in[5];
    const float* msg_w1  = (const float*)d_in[6];
    const float* msg_b1  = (const float*)d_in[7];
    const float* msg_w2  = (const float*)d_in[8];
    const float* msg_b2  = (const float*)d_in[9];
    const float* msg_dw  = (const float*)d_in[10];
    const float* msg_db  = (const float*)d_in[11];
    const float* upd_u   = (const float*)d_in[12];
    const float* upd_v   = (const float*)d_in[13];
    const float* upd_w1  = (const float*)d_in[14];
    const float* upd_b1  = (const float*)d_in[15];
    const float* upd_w2  = (const float*)d_in[16];
    const float* upd_b2  = (const float*)d_in[17];
    const float* edge_w1 = (const float*)d_in[18];
    const float* edge_b1 = (const float*)d_in[19];
    const float* edge_w2 = (const float*)d_in[20];
    const float* edge_b2 = (const float*)d_in[21];
    const float* ro_w1   = (const float*)d_in[22];
    const float* ro_b1   = (const float*)d_in[23];
    const float* ro_w2   = (const float*)d_in[24];
    const float* ro_b2   = (const float*)d_in[25];
    float* out = (float*)d_out;

    float *p_rbf, *p_env, *p_eij, *p_s, *p_phi, *p_h1, *p_stk, *p_spl, *p_t;
    cudaGetSymbolAddress((void**)&p_rbf,  g_rbf);
    cudaGetSymbolAddress((void**)&p_env,  g_env);
    cudaGetSymbolAddress((void**)&p_eij,  g_eij);
    cudaGetSymbolAddress((void**)&p_s,    g_s);
    cudaGetSymbolAddress((void**)&p_phi,  g_phi);
    cudaGetSymbolAddress((void**)&p_h1,   g_h1);
    cudaGetSymbolAddress((void**)&p_stk,  g_stk);
    cudaGetSymbolAddress((void**)&p_spl,  g_spl);
    cudaGetSymbolAddress((void**)&p_t,    g_t);

    const int SMEM_HM = 4 * 128 * HP * 2;    // 73728
    const int SMEM_RO = 4 * 128 * HP2 * 2;   // 139264
    cudaFuncSetAttribute(hmma_gemm<128, false, true,  false>,
                         cudaFuncAttributeMaxDynamicSharedMemorySize, SMEM_HM);
    cudaFuncSetAttribute(hmma_gemm<128, false, false, false>,
                         cudaFuncAttributeMaxDynamicSharedMemorySize, SMEM_HM);
    cudaFuncSetAttribute(hmma_gemm<256, false, true,  false>,
                         cudaFuncAttributeMaxDynamicSharedMemorySize, SMEM_HM);
    cudaFuncSetAttribute(hmma_gemm<256, true,  false, true>,
                         cudaFuncAttributeMaxDynamicSharedMemorySize, SMEM_HM);
    cudaFuncSetAttribute(readout_mma,
                         cudaFuncAttributeMaxDynamicSharedMemorySize, SMEM_RO);

    const int gH = (NN + 127) / 128;  // 157
    const int gE = EE / 128;          // 2500

    init_kernel<<<2048, 256>>>(emb, z, out);
    prep_kernel<<<(EE + 255) / 256, 256>>>(xyz, nbrs);

    // CSR build
    zero_rowptr<<<(NN + 256) / 256, 256>>>();
    hist_kernel<<<(EE + 255) / 256, 256>>>(nbrs);
    scan_kernel<<<1, 1024>>>();
    cursor_init<<<(NN + 255) / 256, 256>>>();
    scatter_kernel<<<(EE + 255) / 256, 256>>>(nbrs);

    // e_ij = (rbf @ de_w + de_b) * env
    mlp_gemm_small<RB, 128><<<(EE + 31) / 32, 128>>>(p_rbf, de_w, de_b, p_eij, p_env, EE);

    for (int l = 0; l < 3; l++) {
        int sel = l & 1;
        int cur = sel ^ 1;

        // phi = swish(s @ msg_w1 + b1) @ msg_w2 + b2
        hmma_gemm<128, false, true, false><<<dim3(gH, 1), 256, SMEM_HM>>>(
            p_s, msg_w1 + l * 128 * 128, 128, msg_b1 + l * 128, 1.f, p_h1, nullptr, NN);
        hmma_gemm<128, false, false, false><<<dim3(gH, 3), 256, SMEM_HM>>>(
            p_h1, msg_w2 + l * 128 * 384, 384, msg_b2 + l * 384, 1.f, p_phi, nullptr, NN);

        // CSR message pass (smem-staged)
        msg2_kernel<<<NN, 128>>>(nbrs, msg_dw + l * RB * 384, msg_db + l * 384, sel);

        // update block
        upd1_kernel<<<(NN + TA - 1) / TA, 128>>>(upd_u + l * 128 * 128,
                                                 upd_v + l * 128 * 128, cur);
        hmma_gemm<256, false, true, false><<<dim3(gH, 1), 256, SMEM_HM>>>(
            p_stk, upd_w1 + l * 256 * 128, 128, upd_b1 + l * 128, 1.f, p_h1, nullptr, NN);
        hmma_gemm<128, false, false, false><<<dim3(gH, 3), 256, SMEM_HM>>>(
            p_h1, upd_w2 + l * 128 * 384, 384, upd_b2 + l * 384, 1.f, p_spl, nullptr, NN);
        apply_kernel<<<(NN * 128 + 255) / 256, 256>>>(cur);

        // edge MLP (factored)
        hmma_gemm<128, false, false, false><<<dim3(gH, 2), 256, SMEM_HM>>>(
            p_s, edge_w1 + l * 128 * 256, 256, edge_b1 + l * 256, 0.5f, p_t, nullptr, NN);
        hmma_gemm<256, true, false, true><<<dim3(gE, 1), 256, SMEM_HM>>>(
            p_t, edge_w2 + l * 256 * 128, 128, edge_b2 + l * 128, 1.f, p_eij, nbrs, EE);
    }

    // fused HMMA readout
    readout_mma<<<gE, 256, SMEM_RO>>>(ro_w1, ro_b1, ro_w2, ro_b2, nbrs, out);

    (void)in_sizes; (void)n_in; (void)out_size;
}